// round 1
// baseline (speedup 1.0000x reference)
#include <cuda_runtime.h>
#include <cstdint>
#include <cstdio>

#define NTOK  8192
#define CDIM  768
#define C3    2304
#define DFF   3072
#define NSLOT 16384
#define NEXP  8
#define TSEQ  2048
#define NH    12
#define HD    64

// ---------------- scratch (static device globals; no allocations) ----------------
__device__ float g_h  [NTOK * CDIM];
__device__ float g_qkv[(size_t)NTOK * C3];
__device__ float g_y  [NTOK * CDIM];
__device__ float g_x1 [NTOK * CDIM];
__device__ float g_z  [NTOK * CDIM];
__device__ float g_hid[(size_t)NSLOT * DFF];
__device__ float g_ye [(size_t)NSLOT * CDIM];
__device__ float g_wgt[NTOK * 2];
__device__ int   g_eidx[NTOK * 2];
__device__ int   g_slot[NTOK * 2];
__device__ int   g_tok[NSLOT];
__device__ int   g_cnt[NEXP];
__device__ int   g_off[NEXP];
__device__ int   g_cur[NEXP];

// ---------------- LayerNorm: one block per row, C=768, 256 threads ----------------
__global__ __launch_bounds__(256) void ln_kernel(
    const float* __restrict__ x, const float* __restrict__ gam,
    const float* __restrict__ bet, float* __restrict__ out)
{
    const int row = blockIdx.x;
    const float* xr = x + (size_t)row * CDIM;
    float vals[3];
    float s1 = 0.f, s2 = 0.f;
#pragma unroll
    for (int u = 0; u < 3; u++) {
        float v = xr[threadIdx.x + u * 256];
        vals[u] = v; s1 += v; s2 += v * v;
    }
#pragma unroll
    for (int off = 16; off; off >>= 1) {
        s1 += __shfl_xor_sync(0xffffffffu, s1, off);
        s2 += __shfl_xor_sync(0xffffffffu, s2, off);
    }
    __shared__ float red1[8], red2[8];
    __shared__ float m_sh, r_sh;
    const int wid = threadIdx.x >> 5, lane = threadIdx.x & 31;
    if (lane == 0) { red1[wid] = s1; red2[wid] = s2; }
    __syncthreads();
    if (threadIdx.x == 0) {
        float a = 0.f, b = 0.f;
#pragma unroll
        for (int w = 0; w < 8; w++) { a += red1[w]; b += red2[w]; }
        float mean = a / CDIM;
        float var  = b / CDIM - mean * mean;
        m_sh = mean; r_sh = rsqrtf(var + 1e-5f);
    }
    __syncthreads();
    const float mean = m_sh, rstd = r_sh;
    float* orow = out + (size_t)row * CDIM;
#pragma unroll
    for (int u = 0; u < 3; u++) {
        int c = threadIdx.x + u * 256;
        orow[c] = (vals[u] - mean) * rstd * gam[c] + bet[c];
    }
}

// ---------------- generic 128x128x8 SGEMM (M,N multiples of 128, K of 8) ----------
template<bool BIAS, bool RESID>
__global__ __launch_bounds__(256) void sgemm128(
    const float* __restrict__ A, const float* __restrict__ Bm,
    const float* __restrict__ bias, const float* __restrict__ resid,
    float* __restrict__ Cm, int M, int N, int K)
{
    __shared__ float As[8][128];
    __shared__ float Bs[8][128];
    const int tid = threadIdx.x;
    const int tx = tid & 15, ty = tid >> 4;
    const int rowBase = blockIdx.y * 128;
    const int colBase = blockIdx.x * 128;
    const int aRow = tid >> 1;
    const int aK4  = (tid & 1) * 4;
    const int bK   = tid >> 5;
    const int bN4  = (tid & 31) * 4;
    const float* Aptr = A + (size_t)(rowBase + aRow) * K + aK4;
    const float* Bptr = Bm + (size_t)bK * N + colBase + bN4;

    float acc[8][8];
#pragma unroll
    for (int i = 0; i < 8; i++)
#pragma unroll
        for (int j = 0; j < 8; j++) acc[i][j] = 0.f;

    for (int k0 = 0; k0 < K; k0 += 8) {
        float4 a = *(const float4*)(Aptr + k0);
        As[aK4 + 0][aRow] = a.x; As[aK4 + 1][aRow] = a.y;
        As[aK4 + 2][aRow] = a.z; As[aK4 + 3][aRow] = a.w;
        *(float4*)&Bs[bK][bN4] = *(const float4*)(Bptr + (size_t)k0 * N);
        __syncthreads();
#pragma unroll
        for (int kk = 0; kk < 8; kk++) {
            float ar[8], br[8];
#pragma unroll
            for (int i = 0; i < 8; i++) ar[i] = As[kk][ty * 8 + i];
#pragma unroll
            for (int j = 0; j < 8; j++) br[j] = Bs[kk][tx * 8 + j];
#pragma unroll
            for (int i = 0; i < 8; i++)
#pragma unroll
                for (int j = 0; j < 8; j++) acc[i][j] += ar[i] * br[j];
        }
        __syncthreads();
    }
#pragma unroll
    for (int i = 0; i < 8; i++) {
        int row = rowBase + ty * 8 + i;
        float* co = Cm + (size_t)row * N + colBase + tx * 8;
        const float* ro = RESID ? resid + (size_t)row * N + colBase + tx * 8 : nullptr;
#pragma unroll
        for (int j4 = 0; j4 < 8; j4 += 4) {
            float4 v;
            v.x = acc[i][j4 + 0]; v.y = acc[i][j4 + 1];
            v.z = acc[i][j4 + 2]; v.w = acc[i][j4 + 3];
            if (BIAS) {
                const float* bp = bias + colBase + tx * 8 + j4;
                v.x += bp[0]; v.y += bp[1]; v.z += bp[2]; v.w += bp[3];
            }
            if (RESID) {
                float4 rv = *(const float4*)(ro + j4);
                v.x += rv.x; v.y += rv.y; v.z += rv.z; v.w += rv.w;
            }
            *(float4*)(co + j4) = v;
        }
    }
}

// ---------------- flash attention: 64-row Q tiles, online softmax ------------------
#define ATTN_SMEM (4 * 64 * 65 * 4)
__global__ __launch_bounds__(256) void attn_kernel(
    const float* __restrict__ qkv, float* __restrict__ y)
{
    extern __shared__ float sm[];
    float* Qs = sm;                 // [64][65]
    float* Ks = Qs + 64 * 65;
    float* Vs = Ks + 64 * 65;
    float* Ps = Vs + 64 * 65;

    const int qt = blockIdx.x;     // query tile (T/64 = 32)
    const int h  = blockIdx.y;
    const int b  = blockIdx.z;
    const int tid = threadIdx.x;
    const int r  = tid >> 2;       // query row within tile
    const int c0 = (tid & 3) * 16; // 16-col chunk

    const int qRow0 = qt * 64;
    const float* qbase = qkv + (size_t)b * TSEQ * C3 + h * HD;

    // load Q tile
#pragma unroll
    for (int u = 0; u < 4; u++) {
        int lin = tid + u * 256;
        int rr = lin >> 4;
        int cc = (lin & 15) * 4;
        float4 v4 = *(const float4*)(qbase + (size_t)(qRow0 + rr) * C3 + cc);
        Qs[rr * 65 + cc + 0] = v4.x; Qs[rr * 65 + cc + 1] = v4.y;
        Qs[rr * 65 + cc + 2] = v4.z; Qs[rr * 65 + cc + 3] = v4.w;
    }

    float o[16];
#pragma unroll
    for (int i = 0; i < 16; i++) o[i] = 0.f;
    float m = -1e30f, l = 0.f;
    const float scale = 0.125f;  // 1/sqrt(64)

    for (int j0 = 0; j0 <= qRow0; j0 += 64) {
        __syncthreads();  // prev-iter Ps/Vs reads done
#pragma unroll
        for (int u = 0; u < 4; u++) {
            int lin = tid + u * 256;
            int rr = lin >> 4;
            int cc = (lin & 15) * 4;
            const float* kb = qbase + CDIM  + (size_t)(j0 + rr) * C3 + cc;
            const float* vb = qbase + 2*CDIM + (size_t)(j0 + rr) * C3 + cc;
            float4 k4 = *(const float4*)kb;
            float4 v4 = *(const float4*)vb;
            Ks[rr * 65 + cc + 0] = k4.x; Ks[rr * 65 + cc + 1] = k4.y;
            Ks[rr * 65 + cc + 2] = k4.z; Ks[rr * 65 + cc + 3] = k4.w;
            Vs[rr * 65 + cc + 0] = v4.x; Vs[rr * 65 + cc + 1] = v4.y;
            Vs[rr * 65 + cc + 2] = v4.z; Vs[rr * 65 + cc + 3] = v4.w;
        }
        __syncthreads();

        float s[16];
#pragma unroll
        for (int i = 0; i < 16; i++) s[i] = 0.f;
        for (int d = 0; d < 64; d++) {
            float qv = Qs[r * 65 + d];
#pragma unroll
            for (int i = 0; i < 16; i++) s[i] += qv * Ks[(c0 + i) * 65 + d];
        }
        const int qg = qRow0 + r;
        float mloc = -1e30f;
#pragma unroll
        for (int i = 0; i < 16; i++) {
            int kg = j0 + c0 + i;
            s[i] = (kg <= qg) ? s[i] * scale : -1e30f;
            mloc = fmaxf(mloc, s[i]);
        }
        mloc = fmaxf(mloc, __shfl_xor_sync(0xffffffffu, mloc, 1));
        mloc = fmaxf(mloc, __shfl_xor_sync(0xffffffffu, mloc, 2));
        float mnew = fmaxf(m, mloc);
        float alpha = __expf(m - mnew);
        float ssum = 0.f;
#pragma unroll
        for (int i = 0; i < 16; i++) {
            float p = __expf(s[i] - mnew);
            Ps[r * 65 + c0 + i] = p;
            ssum += p;
        }
        ssum += __shfl_xor_sync(0xffffffffu, ssum, 1);
        ssum += __shfl_xor_sync(0xffffffffu, ssum, 2);
        l = l * alpha + ssum;
        m = mnew;
#pragma unroll
        for (int i = 0; i < 16; i++) o[i] *= alpha;
        __syncthreads();
        for (int kk = 0; kk < 64; kk++) {
            float p = Ps[r * 65 + kk];
#pragma unroll
            for (int i = 0; i < 16; i++) o[i] += p * Vs[kk * 65 + c0 + i];
        }
    }

    const float inv = 1.f / l;
    float* yb = y + (size_t)(b * TSEQ + qRow0 + r) * CDIM + h * HD + c0;
#pragma unroll
    for (int i = 0; i < 16; i++) yb[i] = o[i] * inv;
}

// ---------------- router: 1 warp per token, top-2 + softmax ------------------------
__global__ __launch_bounds__(256) void router_kernel(
    const float* __restrict__ z, const float* __restrict__ Wr,
    const float* __restrict__ br)
{
    const int warp = (blockIdx.x * blockDim.x + threadIdx.x) >> 5;
    const int lane = threadIdx.x & 31;
    if (warp >= NTOK) return;
    const float* zr = z + (size_t)warp * CDIM;
    float p[NEXP];
#pragma unroll
    for (int e = 0; e < NEXP; e++) p[e] = 0.f;
    for (int c = lane; c < CDIM; c += 32) {
        float zv = zr[c];
        const float* wrow = Wr + c * NEXP;
#pragma unroll
        for (int e = 0; e < NEXP; e++) p[e] += zv * wrow[e];
    }
#pragma unroll
    for (int off = 16; off; off >>= 1)
#pragma unroll
        for (int e = 0; e < NEXP; e++) p[e] += __shfl_xor_sync(0xffffffffu, p[e], off);
    if (lane == 0) {
        float lg[NEXP];
#pragma unroll
        for (int e = 0; e < NEXP; e++) lg[e] = p[e] + br[e];
        int e0 = 0;
#pragma unroll
        for (int e = 1; e < NEXP; e++) if (lg[e] > lg[e0]) e0 = e;
        int e1 = (e0 == 0) ? 1 : 0;
#pragma unroll
        for (int e = 0; e < NEXP; e++) if (e != e0 && lg[e] > lg[e1]) e1 = e;
        float w0 = 1.f / (1.f + __expf(lg[e1] - lg[e0]));
        g_wgt[warp * 2] = w0;
        g_wgt[warp * 2 + 1] = 1.f - w0;
        g_eidx[warp * 2] = e0;
        g_eidx[warp * 2 + 1] = e1;
        atomicAdd(&g_cnt[e0], 1);
        atomicAdd(&g_cnt[e1], 1);
    }
}

__global__ void zero_kernel() {
    int t = threadIdx.x;
    if (t < NEXP) { g_cnt[t] = 0; g_cur[t] = 0; }
}

__global__ void prefix_kernel() {
    int s = 0;
    for (int e = 0; e < NEXP; e++) { g_off[e] = s; s += g_cnt[e]; }
}

__global__ __launch_bounds__(256) void assign_kernel() {
    int n = blockIdx.x * blockDim.x + threadIdx.x;
    if (n >= NTOK) return;
#pragma unroll
    for (int k = 0; k < 2; k++) {
        int e = g_eidx[n * 2 + k];
        int pos = atomicAdd(&g_cur[e], 1);
        int slot = g_off[e] + pos;
        g_slot[n * 2 + k] = slot;
        g_tok[slot] = n;
    }
}

// ---------------- MoE grouped GEMM 1: hid = relu(z_gathered @ W1[e] + b1[e]) -------
__global__ __launch_bounds__(256) void moe_gemm1(
    const float* __restrict__ z, const float* __restrict__ W1,
    const float* __restrict__ b1)
{
    const int e = blockIdx.z;
    const int cnt = g_cnt[e];
    const int m0 = blockIdx.y * 128;
    if (m0 >= cnt) return;
    const int base = g_off[e];
    const float* Bm = W1 + (size_t)e * CDIM * DFF;
    const int colBase = blockIdx.x * 128;
    const int tid = threadIdx.x;
    const int tx = tid & 15, ty = tid >> 4;
    const int aRow = tid >> 1;
    const int aK4  = (tid & 1) * 4;
    const int bK   = tid >> 5;
    const int bN4  = (tid & 31) * 4;
    const int myTok = (m0 + aRow < cnt) ? g_tok[base + m0 + aRow] : -1;
    const float* Aptr = (myTok >= 0) ? z + (size_t)myTok * CDIM + aK4 : nullptr;
    const float* Bptr = Bm + (size_t)bK * DFF + colBase + bN4;

    __shared__ float As[8][128];
    __shared__ float Bs[8][128];
    float acc[8][8];
#pragma unroll
    for (int i = 0; i < 8; i++)
#pragma unroll
        for (int j = 0; j < 8; j++) acc[i][j] = 0.f;

    for (int k0 = 0; k0 < CDIM; k0 += 8) {
        float4 a = make_float4(0.f, 0.f, 0.f, 0.f);
        if (myTok >= 0) a = *(const float4*)(Aptr + k0);
        As[aK4 + 0][aRow] = a.x; As[aK4 + 1][aRow] = a.y;
        As[aK4 + 2][aRow] = a.z; As[aK4 + 3][aRow] = a.w;
        *(float4*)&Bs[bK][bN4] = *(const float4*)(Bptr + (size_t)k0 * DFF);
        __syncthreads();
#pragma unroll
        for (int kk = 0; kk < 8; kk++) {
            float ar[8], br[8];
#pragma unroll
            for (int i = 0; i < 8; i++) ar[i] = As[kk][ty * 8 + i];
#pragma unroll
            for (int j = 0; j < 8; j++) br[j] = Bs[kk][tx * 8 + j];
#pragma unroll
            for (int i = 0; i < 8; i++)
#pragma unroll
                for (int j = 0; j < 8; j++) acc[i][j] += ar[i] * br[j];
        }
        __syncthreads();
    }
#pragma unroll
    for (int i = 0; i < 8; i++) {
        int mrow = m0 + ty * 8 + i;
        if (mrow >= cnt) continue;
        float* outp = &g_hid[(size_t)(base + mrow) * DFF + colBase + tx * 8];
        const float* bp = b1 + (size_t)e * DFF + colBase + tx * 8;
#pragma unroll
        for (int j = 0; j < 8; j++)
            outp[j] = fmaxf(acc[i][j] + bp[j], 0.f);
    }
}

// ---------------- MoE grouped GEMM 2: ye = hid @ W2[e] ----------------------------
__global__ __launch_bounds__(256) void moe_gemm2(const float* __restrict__ W2)
{
    const int e = blockIdx.z;
    const int cnt = g_cnt[e];
    const int m0 = blockIdx.y * 128;
    if (m0 >= cnt) return;
    const int base = g_off[e];
    const float* Bm = W2 + (size_t)e * DFF * CDIM;
    const int colBase = blockIdx.x * 128;
    const int tid = threadIdx.x;
    const int tx = tid & 15, ty = tid >> 4;
    const int aRow = tid >> 1;
    const int aK4  = (tid & 1) * 4;
    const int bK   = tid >> 5;
    const int bN4  = (tid & 31) * 4;
    const bool aValid = (m0 + aRow < cnt);
    const float* Aptr = g_hid + (size_t)(base + m0 + aRow) * DFF + aK4;
    const float* Bptr = Bm + (size_t)bK * CDIM + colBase + bN4;

    __shared__ float As[8][128];
    __shared__ float Bs[8][128];
    float acc[8][8];
#pragma unroll
    for (int i = 0; i < 8; i++)
#pragma unroll
        for (int j = 0; j < 8; j++) acc[i][j] = 0.f;

    for (int k0 = 0; k0 < DFF; k0 += 8) {
        float4 a = make_float4(0.f, 0.f, 0.f, 0.f);
        if (aValid) a = *(const float4*)(Aptr + k0);
        As[aK4 + 0][aRow] = a.x; As[aK4 + 1][aRow] = a.y;
        As[aK4 + 2][aRow] = a.z; As[aK4 + 3][aRow] = a.w;
        *(float4*)&Bs[bK][bN4] = *(const float4*)(Bptr + (size_t)k0 * CDIM);
        __syncthreads();
#pragma unroll
        for (int kk = 0; kk < 8; kk++) {
            float ar[8], br[8];
#pragma unroll
            for (int i = 0; i < 8; i++) ar[i] = As[kk][ty * 8 + i];
#pragma unroll
            for (int j = 0; j < 8; j++) br[j] = Bs[kk][tx * 8 + j];
#pragma unroll
            for (int i = 0; i < 8; i++)
#pragma unroll
                for (int j = 0; j < 8; j++) acc[i][j] += ar[i] * br[j];
        }
        __syncthreads();
    }
#pragma unroll
    for (int i = 0; i < 8; i++) {
        int mrow = m0 + ty * 8 + i;
        if (mrow >= cnt) continue;
        float* outp = &g_ye[(size_t)(base + mrow) * CDIM + colBase + tx * 8];
#pragma unroll
        for (int j4 = 0; j4 < 8; j4 += 4) {
            float4 v;
            v.x = acc[i][j4 + 0]; v.y = acc[i][j4 + 1];
            v.z = acc[i][j4 + 2]; v.w = acc[i][j4 + 3];
            *(float4*)(outp + j4) = v;
        }
    }
}

// ---------------- final: out = x1 + sum_k w_k * (ye_k + b2[e_k]) -------------------
__global__ __launch_bounds__(256) void final_kernel(
    const float* __restrict__ b2, float* __restrict__ out)
{
    int i = blockIdx.x * blockDim.x + threadIdx.x;  // float4 index
    const int total = NTOK * CDIM / 4;
    if (i >= total) return;
    int n = i / (CDIM / 4);
    int c = (i % (CDIM / 4)) * 4;
    float w0 = g_wgt[n * 2], w1 = g_wgt[n * 2 + 1];
    int e0 = g_eidx[n * 2], e1 = g_eidx[n * 2 + 1];
    int s0 = g_slot[n * 2], s1 = g_slot[n * 2 + 1];
    float4 xv  = *(const float4*)&g_x1[(size_t)n * CDIM + c];
    float4 y0  = *(const float4*)&g_ye[(size_t)s0 * CDIM + c];
    float4 y1  = *(const float4*)&g_ye[(size_t)s1 * CDIM + c];
    float4 b0  = *(const float4*)&b2[(size_t)e0 * CDIM + c];
    float4 b1v = *(const float4*)&b2[(size_t)e1 * CDIM + c];
    float4 r;
    r.x = xv.x + w0 * (y0.x + b0.x) + w1 * (y1.x + b1v.x);
    r.y = xv.y + w0 * (y0.y + b0.y) + w1 * (y1.y + b1v.y);
    r.z = xv.z + w0 * (y0.z + b0.z) + w1 * (y1.z + b1v.z);
    r.w = xv.w + w0 * (y0.w + b0.w) + w1 * (y1.w + b1v.w);
    *(float4*)&out[(size_t)n * CDIM + c] = r;
}

// ---------------- launch -----------------------------------------------------------
extern "C" void kernel_launch(void* const* d_in, const int* in_sizes, int n_in,
                              void* d_out, int out_size)
{
    const float* x      = (const float*)d_in[0];
    const float* ln1_g  = (const float*)d_in[1];
    const float* ln1_b  = (const float*)d_in[2];
    const float* Wqkv   = (const float*)d_in[3];
    const float* bqkv   = (const float*)d_in[4];
    const float* Wproj  = (const float*)d_in[5];
    const float* bproj  = (const float*)d_in[6];
    const float* ln2_g  = (const float*)d_in[7];
    const float* ln2_b  = (const float*)d_in[8];
    const float* Wr     = (const float*)d_in[9];
    const float* br     = (const float*)d_in[10];
    const float* W1     = (const float*)d_in[11];
    const float* b1     = (const float*)d_in[12];
    const float* W2     = (const float*)d_in[13];
    const float* b2     = (const float*)d_in[14];
    float* out = (float*)d_out;

    static bool inited = false;
    static float *p_h, *p_qkv, *p_y, *p_x1, *p_z;
    if (!inited) {
        cudaGetSymbolAddress((void**)&p_h,   g_h);
        cudaGetSymbolAddress((void**)&p_qkv, g_qkv);
        cudaGetSymbolAddress((void**)&p_y,   g_y);
        cudaGetSymbolAddress((void**)&p_x1,  g_x1);
        cudaGetSymbolAddress((void**)&p_z,   g_z);
        cudaFuncSetAttribute(attn_kernel,
                             cudaFuncAttributeMaxDynamicSharedMemorySize, ATTN_SMEM);
        inited = true;
    }

    // 1. LN1
    ln_kernel<<<NTOK, 256>>>(x, ln1_g, ln1_b, p_h);
    // 2. QKV GEMM [8192,768]x[768,2304]
    sgemm128<true, false><<<dim3(C3 / 128, NTOK / 128), 256>>>(
        p_h, Wqkv, bqkv, nullptr, p_qkv, NTOK, C3, CDIM);
    // 3. flash attention
    attn_kernel<<<dim3(TSEQ / 64, NH, 4), 256, ATTN_SMEM>>>(p_qkv, p_y);
    // 4. proj + residual
    sgemm128<true, true><<<dim3(CDIM / 128, NTOK / 128), 256>>>(
        p_y, Wproj, bproj, x, p_x1, NTOK, CDIM, CDIM);
    // 5. LN2
    ln_kernel<<<NTOK, 256>>>(p_x1, ln2_g, ln2_b, p_z);
    // 6. routing
    zero_kernel<<<1, 32>>>();
    router_kernel<<<NTOK / 8, 256>>>(p_z, Wr, br);
    prefix_kernel<<<1, 1>>>();
    assign_kernel<<<NTOK / 256, 256>>>();
    // 7. MoE grouped GEMMs (sparse: only top-2 expert rows)
    moe_gemm1<<<dim3(DFF / 128, NTOK / 128, NEXP), 256>>>(p_z, W1, b1);
    moe_gemm2<<<dim3(CDIM / 128, NTOK / 128, NEXP), 256>>>(W2);
    // 8. weighted gather + residual
    final_kernel<<<(NTOK * CDIM / 4 + 255) / 256, 256>>>(b2, out);
}

// round 7
// speedup vs baseline: 1.1330x; 1.1330x over previous
#include <cuda_runtime.h>
#include <cstdint>

#define NTOK  8192
#define CDIM  768
#define C3    2304
#define DFF   3072
#define NSLOT 16384
#define NEXP  8
#define TSEQ  2048
#define NH    12
#define HD    64

// ---------------- scratch (static device globals; no allocations) ----------------
__device__ float g_h  [NTOK * CDIM];
__device__ float g_qkv[(size_t)NTOK * C3];
__device__ float g_y  [NTOK * CDIM];
__device__ float g_x1 [NTOK * CDIM];
__device__ float g_z  [NTOK * CDIM];
__device__ float g_hid[(size_t)NSLOT * DFF];
__device__ float g_ye [(size_t)NSLOT * CDIM];
__device__ float g_wgt[NTOK * 2];
__device__ int   g_eidx[NTOK * 2];
__device__ int   g_slot[NTOK * 2];
__device__ int   g_tok[NSLOT];
__device__ int   g_cnt[NEXP];
__device__ int   g_off[NEXP];
__device__ int   g_cur[NEXP];

// ---------------- helpers ----------------------------------------------------------
__device__ __forceinline__ float tf32cvt(float x) {
    uint32_t o;
    asm("cvt.rna.tf32.f32 %0, %1;" : "=r"(o) : "f"(x));
    return __uint_as_float(o);
}

__device__ __forceinline__ void mma_tf32(float* c, const float* a, const float* b) {
    asm volatile(
        "mma.sync.aligned.m16n8k8.row.col.f32.tf32.tf32.f32 "
        "{%0,%1,%2,%3}, {%4,%5,%6,%7}, {%8,%9}, {%0,%1,%2,%3};\n"
        : "+f"(c[0]), "+f"(c[1]), "+f"(c[2]), "+f"(c[3])
        : "r"(__float_as_uint(a[0])), "r"(__float_as_uint(a[1])),
          "r"(__float_as_uint(a[2])), "r"(__float_as_uint(a[3])),
          "r"(__float_as_uint(b[0])), "r"(__float_as_uint(b[1])));
}

// ---------------- LayerNorm --------------------------------------------------------
__global__ __launch_bounds__(256) void ln_kernel(
    const float* __restrict__ x, const float* __restrict__ gam,
    const float* __restrict__ bet, float* __restrict__ out)
{
    const int row = blockIdx.x;
    const float* xr = x + (size_t)row * CDIM;
    float vals[3];
    float s1 = 0.f, s2 = 0.f;
#pragma unroll
    for (int u = 0; u < 3; u++) {
        float v = xr[threadIdx.x + u * 256];
        vals[u] = v; s1 += v; s2 += v * v;
    }
#pragma unroll
    for (int off = 16; off; off >>= 1) {
        s1 += __shfl_xor_sync(0xffffffffu, s1, off);
        s2 += __shfl_xor_sync(0xffffffffu, s2, off);
    }
    __shared__ float red1[8], red2[8];
    __shared__ float m_sh, r_sh;
    const int wid = threadIdx.x >> 5, lane = threadIdx.x & 31;
    if (lane == 0) { red1[wid] = s1; red2[wid] = s2; }
    __syncthreads();
    if (threadIdx.x == 0) {
        float a = 0.f, b = 0.f;
#pragma unroll
        for (int w = 0; w < 8; w++) { a += red1[w]; b += red2[w]; }
        float mean = a / CDIM;
        float var  = b / CDIM - mean * mean;
        m_sh = mean; r_sh = rsqrtf(var + 1e-5f);
    }
    __syncthreads();
    const float mean = m_sh, rstd = r_sh;
    float* orow = out + (size_t)row * CDIM;
#pragma unroll
    for (int u = 0; u < 3; u++) {
        int c = threadIdx.x + u * 256;
        orow[c] = (vals[u] - mean) * rstd * gam[c] + bet[c];
    }
}

// ---------------- 3xTF32 tensor-core GEMM (fp32-accurate) --------------------------
// 128x128x32 CTA tile, 8 warps (2x4), warp tile 64x32 via m16n8k8 tf32 mma.
// Each operand split x = hi + lo (both tf32); D = AhiBhi + AhiBlo + AloBhi.
// MODE 0: plain A[M,K].  MODE 1: MoE gather (A row = g_tok[...]).  MODE 2: MoE direct.
#define LDA 40
#define LDB 136
#define GEMM_SMEM ((2 * 128 * LDA + 2 * 32 * LDB) * 4)

template<bool BIAS, bool RELU, bool RESID, int MODE>
__global__ __launch_bounds__(256) void gemm_3xtf32(
    const float* __restrict__ A, const float* __restrict__ Bw,
    const float* __restrict__ bias, const float* __restrict__ resid,
    float* __restrict__ Cm, int N, int K)
{
    extern __shared__ float smem[];
    float* AsH = smem;
    float* AsL = AsH + 128 * LDA;
    float* BsH = AsL + 128 * LDA;
    float* BsL = BsH + 32 * LDB;

    int cnt = 0, base = 0;
    if (MODE) {
        const int e = blockIdx.z;
        cnt = g_cnt[e]; base = g_off[e];
        if ((int)blockIdx.y * 128 >= cnt) return;
        Bw += (size_t)e * K * N;
        if (BIAS) bias += (size_t)e * N;
    }
    const int tid = threadIdx.x;
    const int rowBase = blockIdx.y * 128;
    const int colBase = blockIdx.x * 128;

    // A loader: 2 threads per row, 4 float4 each
    const int am = tid >> 1;
    const int arow = rowBase + am;
    bool aValid = true;
    const float* Arow;
    if (MODE == 1) {
        aValid = (arow < cnt);
        int t = aValid ? g_tok[base + arow] : 0;
        Arow = A + (size_t)t * K;
    } else if (MODE == 2) {
        aValid = (arow < cnt);
        Arow = A + (size_t)(base + (aValid ? arow : 0)) * K;
    } else {
        Arow = A + (size_t)arow * K;
    }
    const int bk = tid >> 5;
    const int bf = tid & 31;
    const float* Bcol = Bw + colBase + bf * 4;

    const int lane = tid & 31, wid = tid >> 5;
    const int g  = lane >> 2;
    const int t4 = lane & 3;
    const int warpM = (wid >> 2) * 64;
    const int warpN = (wid & 3) * 32;

    float c[4][4][4];
#pragma unroll
    for (int i = 0; i < 4; i++)
#pragma unroll
        for (int j = 0; j < 4; j++)
#pragma unroll
            for (int q = 0; q < 4; q++) c[i][j][q] = 0.f;

    float4 apre[4], bpre[4];
#pragma unroll
    for (int u = 0; u < 4; u++) {
        int f4 = u * 2 + (tid & 1);
        apre[u] = aValid ? *(const float4*)(Arow + f4 * 4)
                         : make_float4(0.f, 0.f, 0.f, 0.f);
        bpre[u] = *(const float4*)(Bcol + (size_t)(bk + u * 8) * N);
    }

    auto store_tiles = [&]() {
#pragma unroll
        for (int u = 0; u < 4; u++) {
            int f4 = u * 2 + (tid & 1);
            float4 v = apre[u];
            float4 h, l;
            h.x = tf32cvt(v.x); l.x = tf32cvt(v.x - h.x);
            h.y = tf32cvt(v.y); l.y = tf32cvt(v.y - h.y);
            h.z = tf32cvt(v.z); l.z = tf32cvt(v.z - h.z);
            h.w = tf32cvt(v.w); l.w = tf32cvt(v.w - h.w);
            *(float4*)&AsH[am * LDA + f4 * 4] = h;
            *(float4*)&AsL[am * LDA + f4 * 4] = l;
            v = bpre[u];
            h.x = tf32cvt(v.x); l.x = tf32cvt(v.x - h.x);
            h.y = tf32cvt(v.y); l.y = tf32cvt(v.y - h.y);
            h.z = tf32cvt(v.z); l.z = tf32cvt(v.z - h.z);
            h.w = tf32cvt(v.w); l.w = tf32cvt(v.w - h.w);
            *(float4*)&BsH[(bk + u * 8) * LDB + bf * 4] = h;
            *(float4*)&BsL[(bk + u * 8) * LDB + bf * 4] = l;
        }
    };
    store_tiles();
    __syncthreads();

    for (int k0 = 0; k0 < K; k0 += 32) {
        const bool more = (k0 + 32) < K;
        if (more) {
#pragma unroll
            for (int u = 0; u < 4; u++) {
                int f4 = u * 2 + (tid & 1);
                apre[u] = aValid ? *(const float4*)(Arow + k0 + 32 + f4 * 4)
                                 : make_float4(0.f, 0.f, 0.f, 0.f);
                bpre[u] = *(const float4*)(Bcol + (size_t)(k0 + 32 + bk + u * 8) * N);
            }
        }
#pragma unroll
        for (int ks = 0; ks < 4; ks++) {
            const int kb = ks * 8 + t4;
            float ah[4][4], al[4][4], bh[4][2], bl[4][2];
#pragma unroll
            for (int mt = 0; mt < 4; mt++) {
                int m = warpM + mt * 16 + g;
                ah[mt][0] = AsH[m * LDA + kb];
                ah[mt][1] = AsH[(m + 8) * LDA + kb];
                ah[mt][2] = AsH[m * LDA + kb + 4];
                ah[mt][3] = AsH[(m + 8) * LDA + kb + 4];
                al[mt][0] = AsL[m * LDA + kb];
                al[mt][1] = AsL[(m + 8) * LDA + kb];
                al[mt][2] = AsL[m * LDA + kb + 4];
                al[mt][3] = AsL[(m + 8) * LDA + kb + 4];
            }
#pragma unroll
            for (int nt = 0; nt < 4; nt++) {
                int n = warpN + nt * 8 + g;
                bh[nt][0] = BsH[kb * LDB + n];
                bh[nt][1] = BsH[(kb + 4) * LDB + n];
                bl[nt][0] = BsL[kb * LDB + n];
                bl[nt][1] = BsL[(kb + 4) * LDB + n];
            }
#pragma unroll
            for (int mt = 0; mt < 4; mt++)
#pragma unroll
                for (int nt = 0; nt < 4; nt++) {
                    mma_tf32(c[mt][nt], ah[mt], bl[nt]);
                    mma_tf32(c[mt][nt], al[mt], bh[nt]);
                    mma_tf32(c[mt][nt], ah[mt], bh[nt]);
                }
        }
        if (more) {
            __syncthreads();
            store_tiles();
            __syncthreads();
        }
    }

    // epilogue
#pragma unroll
    for (int mt = 0; mt < 4; mt++) {
        const int r0 = rowBase + warpM + mt * 16 + g;
#pragma unroll
        for (int h = 0; h < 2; h++) {
            const int r = r0 + h * 8;
            if (MODE && r >= cnt) continue;
            const size_t orow = MODE ? (size_t)(base + r) : (size_t)r;
            float* cp = Cm + orow * N;
            const float* rp = RESID ? resid + (size_t)r * N : nullptr;
#pragma unroll
            for (int nt = 0; nt < 4; nt++) {
                const int col = colBase + warpN + nt * 8 + 2 * t4;
                float v0 = c[mt][nt][h * 2 + 0];
                float v1 = c[mt][nt][h * 2 + 1];
                if (BIAS) { v0 += bias[col]; v1 += bias[col + 1]; }
                if (RESID) { v0 += rp[col]; v1 += rp[col + 1]; }
                if (RELU) { v0 = fmaxf(v0, 0.f); v1 = fmaxf(v1, 0.f); }
                float2 vv; vv.x = v0; vv.y = v1;
                *(float2*)(cp + col) = vv;
            }
        }
    }
}

// ---------------- flash attention: 64-row Q tiles, online softmax ------------------
#define ATTN_SMEM (4 * 64 * 65 * 4)
__global__ __launch_bounds__(256) void attn_kernel(
    const float* __restrict__ qkv, float* __restrict__ y)
{
    extern __shared__ float sm[];
    float* Qs = sm;
    float* Ks = Qs + 64 * 65;
    float* Vs = Ks + 64 * 65;
    float* Ps = Vs + 64 * 65;

    const int qt = blockIdx.x;
    const int h  = blockIdx.y;
    const int b  = blockIdx.z;
    const int tid = threadIdx.x;
    const int r  = tid >> 2;
    const int c0 = (tid & 3) * 16;

    const int qRow0 = qt * 64;
    const float* qbase = qkv + (size_t)b * TSEQ * C3 + h * HD;

#pragma unroll
    for (int u = 0; u < 4; u++) {
        int lin = tid + u * 256;
        int rr = lin >> 4;
        int cc = (lin & 15) * 4;
        float4 v4 = *(const float4*)(qbase + (size_t)(qRow0 + rr) * C3 + cc);
        Qs[rr * 65 + cc + 0] = v4.x; Qs[rr * 65 + cc + 1] = v4.y;
        Qs[rr * 65 + cc + 2] = v4.z; Qs[rr * 65 + cc + 3] = v4.w;
    }

    float o[16];
#pragma unroll
    for (int i = 0; i < 16; i++) o[i] = 0.f;
    float m = -1e30f, l = 0.f;
    const float scale = 0.125f;

    for (int j0 = 0; j0 <= qRow0; j0 += 64) {
        __syncthreads();
#pragma unroll
        for (int u = 0; u < 4; u++) {
            int lin = tid + u * 256;
            int rr = lin >> 4;
            int cc = (lin & 15) * 4;
            const float* kb = qbase + CDIM  + (size_t)(j0 + rr) * C3 + cc;
            const float* vb = qbase + 2*CDIM + (size_t)(j0 + rr) * C3 + cc;
            float4 k4 = *(const float4*)kb;
            float4 v4 = *(const float4*)vb;
            Ks[rr * 65 + cc + 0] = k4.x; Ks[rr * 65 + cc + 1] = k4.y;
            Ks[rr * 65 + cc + 2] = k4.z; Ks[rr * 65 + cc + 3] = k4.w;
            Vs[rr * 65 + cc + 0] = v4.x; Vs[rr * 65 + cc + 1] = v4.y;
            Vs[rr * 65 + cc + 2] = v4.z; Vs[rr * 65 + cc + 3] = v4.w;
        }
        __syncthreads();

        float s[16];
#pragma unroll
        for (int i = 0; i < 16; i++) s[i] = 0.f;
        for (int d = 0; d < 64; d++) {
            float qv = Qs[r * 65 + d];
#pragma unroll
            for (int i = 0; i < 16; i++) s[i] += qv * Ks[(c0 + i) * 65 + d];
        }
        const int qg = qRow0 + r;
        float mloc = -1e30f;
#pragma unroll
        for (int i = 0; i < 16; i++) {
            int kg = j0 + c0 + i;
            s[i] = (kg <= qg) ? s[i] * scale : -1e30f;
            mloc = fmaxf(mloc, s[i]);
        }
        mloc = fmaxf(mloc, __shfl_xor_sync(0xffffffffu, mloc, 1));
        mloc = fmaxf(mloc, __shfl_xor_sync(0xffffffffu, mloc, 2));
        float mnew = fmaxf(m, mloc);
        float alpha = __expf(m - mnew);
        float ssum = 0.f;
#pragma unroll
        for (int i = 0; i < 16; i++) {
            float p = __expf(s[i] - mnew);
            Ps[r * 65 + c0 + i] = p;
            ssum += p;
        }
        ssum += __shfl_xor_sync(0xffffffffu, ssum, 1);
        ssum += __shfl_xor_sync(0xffffffffu, ssum, 2);
        l = l * alpha + ssum;
        m = mnew;
#pragma unroll
        for (int i = 0; i < 16; i++) o[i] *= alpha;
        __syncthreads();
        for (int kk = 0; kk < 64; kk++) {
            float p = Ps[r * 65 + kk];
#pragma unroll
            for (int i = 0; i < 16; i++) o[i] += p * Vs[kk * 65 + c0 + i];
        }
    }

    const float inv = 1.f / l;
    float* yb = y + (size_t)(b * TSEQ + qRow0 + r) * CDIM + h * HD + c0;
#pragma unroll
    for (int i = 0; i < 16; i++) yb[i] = o[i] * inv;
}

// ---------------- router -----------------------------------------------------------
__global__ __launch_bounds__(256) void router_kernel(
    const float* __restrict__ z, const float* __restrict__ Wr,
    const float* __restrict__ br)
{
    const int warp = (blockIdx.x * blockDim.x + threadIdx.x) >> 5;
    const int lane = threadIdx.x & 31;
    if (warp >= NTOK) return;
    const float* zr = z + (size_t)warp * CDIM;
    float p[NEXP];
#pragma unroll
    for (int e = 0; e < NEXP; e++) p[e] = 0.f;
    for (int c = lane; c < CDIM; c += 32) {
        float zv = zr[c];
        const float* wrow = Wr + c * NEXP;
#pragma unroll
        for (int e = 0; e < NEXP; e++) p[e] += zv * wrow[e];
    }
#pragma unroll
    for (int off = 16; off; off >>= 1)
#pragma unroll
        for (int e = 0; e < NEXP; e++) p[e] += __shfl_xor_sync(0xffffffffu, p[e], off);
    if (lane == 0) {
        float lg[NEXP];
#pragma unroll
        for (int e = 0; e < NEXP; e++) lg[e] = p[e] + br[e];
        int e0 = 0;
#pragma unroll
        for (int e = 1; e < NEXP; e++) if (lg[e] > lg[e0]) e0 = e;
        int e1 = (e0 == 0) ? 1 : 0;
#pragma unroll
        for (int e = 0; e < NEXP; e++) if (e != e0 && lg[e] > lg[e1]) e1 = e;
        float w0 = 1.f / (1.f + __expf(lg[e1] - lg[e0]));
        g_wgt[warp * 2] = w0;
        g_wgt[warp * 2 + 1] = 1.f - w0;
        g_eidx[warp * 2] = e0;
        g_eidx[warp * 2 + 1] = e1;
        atomicAdd(&g_cnt[e0], 1);
        atomicAdd(&g_cnt[e1], 1);
    }
}

__global__ void zero_kernel() {
    int t = threadIdx.x;
    if (t < NEXP) { g_cnt[t] = 0; g_cur[t] = 0; }
}

__global__ void prefix_kernel() {
    int s = 0;
    for (int e = 0; e < NEXP; e++) { g_off[e] = s; s += g_cnt[e]; }
}

__global__ __launch_bounds__(256) void assign_kernel() {
    int n = blockIdx.x * blockDim.x + threadIdx.x;
    if (n >= NTOK) return;
#pragma unroll
    for (int k = 0; k < 2; k++) {
        int e = g_eidx[n * 2 + k];
        int pos = atomicAdd(&g_cur[e], 1);
        int slot = g_off[e] + pos;
        g_slot[n * 2 + k] = slot;
        g_tok[slot] = n;
    }
}

// ---------------- final: out = x1 + sum_k w_k * (ye_k + b2[e_k]) -------------------
__global__ __launch_bounds__(256) void final_kernel(
    const float* __restrict__ b2, float* __restrict__ out)
{
    int i = blockIdx.x * blockDim.x + threadIdx.x;
    const int total = NTOK * CDIM / 4;
    if (i >= total) return;
    int n = i / (CDIM / 4);
    int c = (i % (CDIM / 4)) * 4;
    float w0 = g_wgt[n * 2], w1 = g_wgt[n * 2 + 1];
    int e0 = g_eidx[n * 2], e1 = g_eidx[n * 2 + 1];
    int s0 = g_slot[n * 2], s1 = g_slot[n * 2 + 1];
    float4 xv  = *(const float4*)&g_x1[(size_t)n * CDIM + c];
    float4 y0  = *(const float4*)&g_ye[(size_t)s0 * CDIM + c];
    float4 y1  = *(const float4*)&g_ye[(size_t)s1 * CDIM + c];
    float4 b0  = *(const float4*)&b2[(size_t)e0 * CDIM + c];
    float4 b1v = *(const float4*)&b2[(size_t)e1 * CDIM + c];
    float4 r;
    r.x = xv.x + w0 * (y0.x + b0.x) + w1 * (y1.x + b1v.x);
    r.y = xv.y + w0 * (y0.y + b0.y) + w1 * (y1.y + b1v.y);
    r.z = xv.z + w0 * (y0.z + b0.z) + w1 * (y1.z + b1v.z);
    r.w = xv.w + w0 * (y0.w + b0.w) + w1 * (y1.w + b1v.w);
    *(float4*)&out[(size_t)n * CDIM + c] = r;
}

// ---------------- launch -----------------------------------------------------------
extern "C" void kernel_launch(void* const* d_in, const int* in_sizes, int n_in,
                              void* d_out, int out_size)
{
    const float* x      = (const float*)d_in[0];
    const float* ln1_g  = (const float*)d_in[1];
    const float* ln1_b  = (const float*)d_in[2];
    const float* Wqkv   = (const float*)d_in[3];
    const float* bqkv   = (const float*)d_in[4];
    const float* Wproj  = (const float*)d_in[5];
    const float* bproj  = (const float*)d_in[6];
    const float* ln2_g  = (const float*)d_in[7];
    const float* ln2_b  = (const float*)d_in[8];
    const float* Wr     = (const float*)d_in[9];
    const float* br     = (const float*)d_in[10];
    const float* W1     = (const float*)d_in[11];
    const float* b1     = (const float*)d_in[12];
    const float* W2     = (const float*)d_in[13];
    const float* b2     = (const float*)d_in[14];
    float* out = (float*)d_out;

    static bool inited = false;
    static float *p_h, *p_qkv, *p_y, *p_x1, *p_z, *p_hid, *p_ye;
    if (!inited) {
        cudaGetSymbolAddress((void**)&p_h,   g_h);
        cudaGetSymbolAddress((void**)&p_qkv, g_qkv);
        cudaGetSymbolAddress((void**)&p_y,   g_y);
        cudaGetSymbolAddress((void**)&p_x1,  g_x1);
        cudaGetSymbolAddress((void**)&p_z,   g_z);
        cudaGetSymbolAddress((void**)&p_hid, g_hid);
        cudaGetSymbolAddress((void**)&p_ye,  g_ye);
        cudaFuncSetAttribute(attn_kernel,
                             cudaFuncAttributeMaxDynamicSharedMemorySize, ATTN_SMEM);
        cudaFuncSetAttribute(gemm_3xtf32<true, false, false, 0>,
                             cudaFuncAttributeMaxDynamicSharedMemorySize, GEMM_SMEM);
        cudaFuncSetAttribute(gemm_3xtf32<true, false, true, 0>,
                             cudaFuncAttributeMaxDynamicSharedMemorySize, GEMM_SMEM);
        cudaFuncSetAttribute(gemm_3xtf32<true, true, false, 1>,
                             cudaFuncAttributeMaxDynamicSharedMemorySize, GEMM_SMEM);
        cudaFuncSetAttribute(gemm_3xtf32<false, false, false, 2>,
                             cudaFuncAttributeMaxDynamicSharedMemorySize, GEMM_SMEM);
        inited = true;
    }

    // 1. LN1
    ln_kernel<<<NTOK, 256>>>(x, ln1_g, ln1_b, p_h);
    // 2. QKV GEMM [8192,768]x[768,2304] (3xTF32 tensor cores)
    gemm_3xtf32<true, false, false, 0><<<dim3(C3 / 128, NTOK / 128), 256, GEMM_SMEM>>>(
        p_h, Wqkv, bqkv, nullptr, p_qkv, C3, CDIM);
    // 3. flash attention
    attn_kernel<<<dim3(TSEQ / 64, NH, 4), 256, ATTN_SMEM>>>(p_qkv, p_y);
    // 4. proj + residual
    gemm_3xtf32<true, false, true, 0><<<dim3(CDIM / 128, NTOK / 128), 256, GEMM_SMEM>>>(
        p_y, Wproj, bproj, x, p_x1, CDIM, CDIM);
    // 5. LN2
    ln_kernel<<<NTOK, 256>>>(p_x1, ln2_g, ln2_b, p_z);
    // 6. routing
    zero_kernel<<<1, 32>>>();
    router_kernel<<<NTOK / 8, 256>>>(p_z, Wr, br);
    prefix_kernel<<<1, 1>>>();
    assign_kernel<<<NTOK / 256, 256>>>();
    // 7. MoE grouped GEMMs (sparse top-2, 3xTF32 tensor cores)
    gemm_3xtf32<true, true, false, 1><<<dim3(DFF / 128, NTOK / 128, NEXP), 256, GEMM_SMEM>>>(
        p_z, W1, b1, nullptr, p_hid, DFF, CDIM);
    gemm_3xtf32<false, false, false, 2><<<dim3(CDIM / 128, NTOK / 128, NEXP), 256, GEMM_SMEM>>>(
        p_hid, W2, nullptr, nullptr, p_ye, CDIM, DFF);
    // 8. weighted gather + residual
    final_kernel<<<(NTOK * CDIM / 4 + 255) / 256, 256>>>(b2, out);
}

// round 8
// speedup vs baseline: 1.2263x; 1.0823x over previous
#include <cuda_runtime.h>
#include <cstdint>

#define NTOK  8192
#define CDIM  768
#define C3    2304
#define DFF   3072
#define NSLOT 16384
#define NEXP  8
#define TSEQ  2048
#define NH    12
#define HD    64

// ---------------- scratch (static device globals; no allocations) ----------------
__device__ float g_h  [NTOK * CDIM];
__device__ float g_qkv[(size_t)NTOK * C3];
__device__ float g_y  [NTOK * CDIM];
__device__ float g_x1 [NTOK * CDIM];
__device__ float g_z  [NTOK * CDIM];
__device__ float g_hid[(size_t)NSLOT * DFF];
__device__ float g_ye [(size_t)NSLOT * CDIM];
__device__ float g_wgt[NTOK * 2];
__device__ int   g_eidx[NTOK * 2];
__device__ int   g_slot[NTOK * 2];
__device__ int   g_tok[NSLOT];
__device__ int   g_cnt[NEXP];
__device__ int   g_off[NEXP];
__device__ int   g_cur[NEXP];

// ---------------- helpers ----------------------------------------------------------
__device__ __forceinline__ float tf32cvt(float x) {
    uint32_t o;
    asm("cvt.rna.tf32.f32 %0, %1;" : "=r"(o) : "f"(x));
    return __uint_as_float(o);
}

__device__ __forceinline__ void mma_tf32(float* c, const float* a, const float* b) {
    asm volatile(
        "mma.sync.aligned.m16n8k8.row.col.f32.tf32.tf32.f32 "
        "{%0,%1,%2,%3}, {%4,%5,%6,%7}, {%8,%9}, {%0,%1,%2,%3};\n"
        : "+f"(c[0]), "+f"(c[1]), "+f"(c[2]), "+f"(c[3])
        : "r"(__float_as_uint(a[0])), "r"(__float_as_uint(a[1])),
          "r"(__float_as_uint(a[2])), "r"(__float_as_uint(a[3])),
          "r"(__float_as_uint(b[0])), "r"(__float_as_uint(b[1])));
}

__device__ __forceinline__ void cp16(float* smemPtr, const float* g, bool valid) {
    uint32_t s = (uint32_t)__cvta_generic_to_shared(smemPtr);
    int sz = valid ? 16 : 0;
    asm volatile("cp.async.ca.shared.global [%0], [%1], 16, %2;\n"
                 :: "r"(s), "l"(g), "r"(sz));
}
__device__ __forceinline__ void cp_commit() {
    asm volatile("cp.async.commit_group;\n");
}
template<int N> __device__ __forceinline__ void cp_wait() {
    asm volatile("cp.async.wait_group %0;\n" :: "n"(N));
}

// ---------------- LayerNorm --------------------------------------------------------
__global__ __launch_bounds__(256) void ln_kernel(
    const float* __restrict__ x, const float* __restrict__ gam,
    const float* __restrict__ bet, float* __restrict__ out)
{
    const int row = blockIdx.x;
    const float* xr = x + (size_t)row * CDIM;
    float vals[3];
    float s1 = 0.f, s2 = 0.f;
#pragma unroll
    for (int u = 0; u < 3; u++) {
        float v = xr[threadIdx.x + u * 256];
        vals[u] = v; s1 += v; s2 += v * v;
    }
#pragma unroll
    for (int off = 16; off; off >>= 1) {
        s1 += __shfl_xor_sync(0xffffffffu, s1, off);
        s2 += __shfl_xor_sync(0xffffffffu, s2, off);
    }
    __shared__ float red1[8], red2[8];
    __shared__ float m_sh, r_sh;
    const int wid = threadIdx.x >> 5, lane = threadIdx.x & 31;
    if (lane == 0) { red1[wid] = s1; red2[wid] = s2; }
    __syncthreads();
    if (threadIdx.x == 0) {
        float a = 0.f, b = 0.f;
#pragma unroll
        for (int w = 0; w < 8; w++) { a += red1[w]; b += red2[w]; }
        float mean = a / CDIM;
        float var  = b / CDIM - mean * mean;
        m_sh = mean; r_sh = rsqrtf(var + 1e-5f);
    }
    __syncthreads();
    const float mean = m_sh, rstd = r_sh;
    float* orow = out + (size_t)row * CDIM;
#pragma unroll
    for (int u = 0; u < 3; u++) {
        int c = threadIdx.x + u * 256;
        orow[c] = (vals[u] - mean) * rstd * gam[c] + bet[c];
    }
}

// ---------------- 3xTF32 tensor-core GEMM (fp32-accurate) --------------------------
// 128x128x32 CTA tile, 8 warps (2x4), warp tile 64x32 via m16n8k8 tf32 mma.
// Raw fp32 in SMEM (cp.async double-buffered); hi/lo split at fragment load.
// D = AhiBhi + AhiBlo + AloBhi.  2 CTAs/SM via launch_bounds(256, 2).
// MODE 0: plain A[M,K].  MODE 1: MoE gather (A row = g_tok[...]).  MODE 2: MoE direct.
#define LDA 36
#define LDB 136
#define STAGE_F (128 * LDA + 32 * LDB)
#define GEMM_SMEM (2 * STAGE_F * 4)

template<bool BIAS, bool RELU, bool RESID, int MODE>
__global__ __launch_bounds__(256, 2) void gemm_3xtf32(
    const float* __restrict__ A, const float* __restrict__ Bw,
    const float* __restrict__ bias, const float* __restrict__ resid,
    float* __restrict__ Cm, int N, int K)
{
    extern __shared__ float smem[];

    int cnt = 0, base = 0;
    if (MODE) {
        const int e = blockIdx.z;
        cnt = g_cnt[e]; base = g_off[e];
        if ((int)blockIdx.y * 128 >= cnt) return;
        Bw += (size_t)e * K * N;
        if (BIAS) bias += (size_t)e * N;
    }
    const int tid = threadIdx.x;
    const int rowBase = blockIdx.y * 128;
    const int colBase = blockIdx.x * 128;

    // A loader: 2 threads per row, 4x 16B each
    const int am = tid >> 1;
    const int arow = rowBase + am;
    bool aValid = true;
    const float* Arow;
    if (MODE == 1) {
        aValid = (arow < cnt);
        int t = aValid ? g_tok[base + arow] : 0;
        Arow = A + (size_t)t * K;
    } else if (MODE == 2) {
        aValid = (arow < cnt);
        Arow = A + (size_t)(base + (aValid ? arow : 0)) * K;
    } else {
        Arow = A + (size_t)arow * K;
    }
    const int bk = tid >> 5;
    const int bf = tid & 31;
    const float* Bcol = Bw + colBase + bf * 4;

    const int lane = tid & 31, wid = tid >> 5;
    const int g  = lane >> 2;
    const int t4 = lane & 3;
    const int warpM = (wid >> 2) * 64;
    const int warpN = (wid & 3) * 32;

    float c[4][4][4];
#pragma unroll
    for (int i = 0; i < 4; i++)
#pragma unroll
        for (int j = 0; j < 4; j++)
#pragma unroll
            for (int q = 0; q < 4; q++) c[i][j][q] = 0.f;

    auto load_stage = [&](int k0, float* As, float* Bs) {
#pragma unroll
        for (int u = 0; u < 4; u++) {
            int f4 = u * 2 + (tid & 1);
            cp16(&As[am * LDA + f4 * 4], Arow + k0 + f4 * 4, aValid);
            cp16(&Bs[(bk + u * 8) * LDB + bf * 4],
                 Bcol + (size_t)(k0 + bk + u * 8) * N, true);
        }
    };

    const int nIters = K / 32;
    load_stage(0, smem, smem + 128 * LDA);
    cp_commit();

    for (int it = 0; it < nIters; it++) {
        float* As = smem + (it & 1) * STAGE_F;
        float* Bs = As + 128 * LDA;
        const bool more = (it + 1) < nIters;
        if (more) {
            float* As2 = smem + ((it + 1) & 1) * STAGE_F;
            load_stage((it + 1) * 32, As2, As2 + 128 * LDA);
            cp_commit();
            cp_wait<1>();
        } else {
            cp_wait<0>();
        }
        __syncthreads();

#pragma unroll
        for (int ks = 0; ks < 4; ks++) {
            const int kb = ks * 8 + t4;
            float bh[4][2], bl[4][2];
#pragma unroll
            for (int nt = 0; nt < 4; nt++) {
                int n = warpN + nt * 8 + g;
                float r0 = Bs[kb * LDB + n];
                float r1 = Bs[(kb + 4) * LDB + n];
                bh[nt][0] = tf32cvt(r0); bl[nt][0] = tf32cvt(r0 - bh[nt][0]);
                bh[nt][1] = tf32cvt(r1); bl[nt][1] = tf32cvt(r1 - bh[nt][1]);
            }
#pragma unroll
            for (int mt = 0; mt < 4; mt++) {
                int m = warpM + mt * 16 + g;
                float r0 = As[m * LDA + kb];
                float r1 = As[(m + 8) * LDA + kb];
                float r2 = As[m * LDA + kb + 4];
                float r3 = As[(m + 8) * LDA + kb + 4];
                float ah[4], al[4];
                ah[0] = tf32cvt(r0); al[0] = tf32cvt(r0 - ah[0]);
                ah[1] = tf32cvt(r1); al[1] = tf32cvt(r1 - ah[1]);
                ah[2] = tf32cvt(r2); al[2] = tf32cvt(r2 - ah[2]);
                ah[3] = tf32cvt(r3); al[3] = tf32cvt(r3 - ah[3]);
#pragma unroll
                for (int nt = 0; nt < 4; nt++) {
                    mma_tf32(c[mt][nt], ah, bl[nt]);
                    mma_tf32(c[mt][nt], al, bh[nt]);
                    mma_tf32(c[mt][nt], ah, bh[nt]);
                }
            }
        }
        __syncthreads();
    }

    // epilogue
#pragma unroll
    for (int mt = 0; mt < 4; mt++) {
        const int r0 = rowBase + warpM + mt * 16 + g;
#pragma unroll
        for (int h = 0; h < 2; h++) {
            const int r = r0 + h * 8;
            if (MODE && r >= cnt) continue;
            const size_t orow = MODE ? (size_t)(base + r) : (size_t)r;
            float* cp = Cm + orow * N;
            const float* rp = RESID ? resid + (size_t)r * N : nullptr;
#pragma unroll
            for (int nt = 0; nt < 4; nt++) {
                const int col = colBase + warpN + nt * 8 + 2 * t4;
                float v0 = c[mt][nt][h * 2 + 0];
                float v1 = c[mt][nt][h * 2 + 1];
                if (BIAS) { v0 += bias[col]; v1 += bias[col + 1]; }
                if (RESID) { v0 += rp[col]; v1 += rp[col + 1]; }
                if (RELU) { v0 = fmaxf(v0, 0.f); v1 = fmaxf(v1, 0.f); }
                float2 vv; vv.x = v0; vv.y = v1;
                *(float2*)(cp + col) = vv;
            }
        }
    }
}

// ---------------- flash attention: 64-row Q tiles, online softmax ------------------
#define ATTN_SMEM (4 * 64 * 65 * 4)
__global__ __launch_bounds__(256) void attn_kernel(
    const float* __restrict__ qkv, float* __restrict__ y)
{
    extern __shared__ float sm[];
    float* Qs = sm;
    float* Ks = Qs + 64 * 65;
    float* Vs = Ks + 64 * 65;
    float* Ps = Vs + 64 * 65;

    const int qt = blockIdx.x;
    const int h  = blockIdx.y;
    const int b  = blockIdx.z;
    const int tid = threadIdx.x;
    const int r  = tid >> 2;
    const int c0 = (tid & 3) * 16;

    const int qRow0 = qt * 64;
    const float* qbase = qkv + (size_t)b * TSEQ * C3 + h * HD;

#pragma unroll
    for (int u = 0; u < 4; u++) {
        int lin = tid + u * 256;
        int rr = lin >> 4;
        int cc = (lin & 15) * 4;
        float4 v4 = *(const float4*)(qbase + (size_t)(qRow0 + rr) * C3 + cc);
        Qs[rr * 65 + cc + 0] = v4.x; Qs[rr * 65 + cc + 1] = v4.y;
        Qs[rr * 65 + cc + 2] = v4.z; Qs[rr * 65 + cc + 3] = v4.w;
    }

    float o[16];
#pragma unroll
    for (int i = 0; i < 16; i++) o[i] = 0.f;
    float m = -1e30f, l = 0.f;
    const float scale = 0.125f;

    for (int j0 = 0; j0 <= qRow0; j0 += 64) {
        __syncthreads();
#pragma unroll
        for (int u = 0; u < 4; u++) {
            int lin = tid + u * 256;
            int rr = lin >> 4;
            int cc = (lin & 15) * 4;
            const float* kb = qbase + CDIM  + (size_t)(j0 + rr) * C3 + cc;
            const float* vb = qbase + 2*CDIM + (size_t)(j0 + rr) * C3 + cc;
            float4 k4 = *(const float4*)kb;
            float4 v4 = *(const float4*)vb;
            Ks[rr * 65 + cc + 0] = k4.x; Ks[rr * 65 + cc + 1] = k4.y;
            Ks[rr * 65 + cc + 2] = k4.z; Ks[rr * 65 + cc + 3] = k4.w;
            Vs[rr * 65 + cc + 0] = v4.x; Vs[rr * 65 + cc + 1] = v4.y;
            Vs[rr * 65 + cc + 2] = v4.z; Vs[rr * 65 + cc + 3] = v4.w;
        }
        __syncthreads();

        float s[16];
#pragma unroll
        for (int i = 0; i < 16; i++) s[i] = 0.f;
        for (int d = 0; d < 64; d++) {
            float qv = Qs[r * 65 + d];
#pragma unroll
            for (int i = 0; i < 16; i++) s[i] += qv * Ks[(c0 + i) * 65 + d];
        }
        const int qg = qRow0 + r;
        float mloc = -1e30f;
#pragma unroll
        for (int i = 0; i < 16; i++) {
            int kg = j0 + c0 + i;
            s[i] = (kg <= qg) ? s[i] * scale : -1e30f;
            mloc = fmaxf(mloc, s[i]);
        }
        mloc = fmaxf(mloc, __shfl_xor_sync(0xffffffffu, mloc, 1));
        mloc = fmaxf(mloc, __shfl_xor_sync(0xffffffffu, mloc, 2));
        float mnew = fmaxf(m, mloc);
        float alpha = __expf(m - mnew);
        float ssum = 0.f;
#pragma unroll
        for (int i = 0; i < 16; i++) {
            float p = __expf(s[i] - mnew);
            Ps[r * 65 + c0 + i] = p;
            ssum += p;
        }
        ssum += __shfl_xor_sync(0xffffffffu, ssum, 1);
        ssum += __shfl_xor_sync(0xffffffffu, ssum, 2);
        l = l * alpha + ssum;
        m = mnew;
#pragma unroll
        for (int i = 0; i < 16; i++) o[i] *= alpha;
        __syncthreads();
        for (int kk = 0; kk < 64; kk++) {
            float p = Ps[r * 65 + kk];
#pragma unroll
            for (int i = 0; i < 16; i++) o[i] += p * Vs[kk * 65 + c0 + i];
        }
    }

    const float inv = 1.f / l;
    float* yb = y + (size_t)(b * TSEQ + qRow0 + r) * CDIM + h * HD + c0;
#pragma unroll
    for (int i = 0; i < 16; i++) yb[i] = o[i] * inv;
}

// ---------------- router -----------------------------------------------------------
__global__ __launch_bounds__(256) void router_kernel(
    const float* __restrict__ z, const float* __restrict__ Wr,
    const float* __restrict__ br)
{
    const int warp = (blockIdx.x * blockDim.x + threadIdx.x) >> 5;
    const int lane = threadIdx.x & 31;
    if (warp >= NTOK) return;
    const float* zr = z + (size_t)warp * CDIM;
    float p[NEXP];
#pragma unroll
    for (int e = 0; e < NEXP; e++) p[e] = 0.f;
    for (int c = lane; c < CDIM; c += 32) {
        float zv = zr[c];
        const float* wrow = Wr + c * NEXP;
#pragma unroll
        for (int e = 0; e < NEXP; e++) p[e] += zv * wrow[e];
    }
#pragma unroll
    for (int off = 16; off; off >>= 1)
#pragma unroll
        for (int e = 0; e < NEXP; e++) p[e] += __shfl_xor_sync(0xffffffffu, p[e], off);
    if (lane == 0) {
        float lg[NEXP];
#pragma unroll
        for (int e = 0; e < NEXP; e++) lg[e] = p[e] + br[e];
        int e0 = 0;
#pragma unroll
        for (int e = 1; e < NEXP; e++) if (lg[e] > lg[e0]) e0 = e;
        int e1 = (e0 == 0) ? 1 : 0;
#pragma unroll
        for (int e = 0; e < NEXP; e++) if (e != e0 && lg[e] > lg[e1]) e1 = e;
        float w0 = 1.f / (1.f + __expf(lg[e1] - lg[e0]));
        g_wgt[warp * 2] = w0;
        g_wgt[warp * 2 + 1] = 1.f - w0;
        g_eidx[warp * 2] = e0;
        g_eidx[warp * 2 + 1] = e1;
        atomicAdd(&g_cnt[e0], 1);
        atomicAdd(&g_cnt[e1], 1);
    }
}

__global__ void zero_kernel() {
    int t = threadIdx.x;
    if (t < NEXP) { g_cnt[t] = 0; g_cur[t] = 0; }
}

__global__ void prefix_kernel() {
    int s = 0;
    for (int e = 0; e < NEXP; e++) { g_off[e] = s; s += g_cnt[e]; }
}

__global__ __launch_bounds__(256) void assign_kernel() {
    int n = blockIdx.x * blockDim.x + threadIdx.x;
    if (n >= NTOK) return;
#pragma unroll
    for (int k = 0; k < 2; k++) {
        int e = g_eidx[n * 2 + k];
        int pos = atomicAdd(&g_cur[e], 1);
        int slot = g_off[e] + pos;
        g_slot[n * 2 + k] = slot;
        g_tok[slot] = n;
    }
}

// ---------------- final: out = x1 + sum_k w_k * (ye_k + b2[e_k]) -------------------
__global__ __launch_bounds__(256) void final_kernel(
    const float* __restrict__ b2, float* __restrict__ out)
{
    int i = blockIdx.x * blockDim.x + threadIdx.x;
    const int total = NTOK * CDIM / 4;
    if (i >= total) return;
    int n = i / (CDIM / 4);
    int c = (i % (CDIM / 4)) * 4;
    float w0 = g_wgt[n * 2], w1 = g_wgt[n * 2 + 1];
    int e0 = g_eidx[n * 2], e1 = g_eidx[n * 2 + 1];
    int s0 = g_slot[n * 2], s1 = g_slot[n * 2 + 1];
    float4 xv  = *(const float4*)&g_x1[(size_t)n * CDIM + c];
    float4 y0  = *(const float4*)&g_ye[(size_t)s0 * CDIM + c];
    float4 y1  = *(const float4*)&g_ye[(size_t)s1 * CDIM + c];
    float4 b0  = *(const float4*)&b2[(size_t)e0 * CDIM + c];
    float4 b1v = *(const float4*)&b2[(size_t)e1 * CDIM + c];
    float4 r;
    r.x = xv.x + w0 * (y0.x + b0.x) + w1 * (y1.x + b1v.x);
    r.y = xv.y + w0 * (y0.y + b0.y) + w1 * (y1.y + b1v.y);
    r.z = xv.z + w0 * (y0.z + b0.z) + w1 * (y1.z + b1v.z);
    r.w = xv.w + w0 * (y0.w + b0.w) + w1 * (y1.w + b1v.w);
    *(float4*)&out[(size_t)n * CDIM + c] = r;
}

// ---------------- launch -----------------------------------------------------------
extern "C" void kernel_launch(void* const* d_in, const int* in_sizes, int n_in,
                              void* d_out, int out_size)
{
    const float* x      = (const float*)d_in[0];
    const float* ln1_g  = (const float*)d_in[1];
    const float* ln1_b  = (const float*)d_in[2];
    const float* Wqkv   = (const float*)d_in[3];
    const float* bqkv   = (const float*)d_in[4];
    const float* Wproj  = (const float*)d_in[5];
    const float* bproj  = (const float*)d_in[6];
    const float* ln2_g  = (const float*)d_in[7];
    const float* ln2_b  = (const float*)d_in[8];
    const float* Wr     = (const float*)d_in[9];
    const float* br     = (const float*)d_in[10];
    const float* W1     = (const float*)d_in[11];
    const float* b1     = (const float*)d_in[12];
    const float* W2     = (const float*)d_in[13];
    const float* b2     = (const float*)d_in[14];
    float* out = (float*)d_out;

    static bool inited = false;
    static float *p_h, *p_qkv, *p_y, *p_x1, *p_z, *p_hid, *p_ye;
    if (!inited) {
        cudaGetSymbolAddress((void**)&p_h,   g_h);
        cudaGetSymbolAddress((void**)&p_qkv, g_qkv);
        cudaGetSymbolAddress((void**)&p_y,   g_y);
        cudaGetSymbolAddress((void**)&p_x1,  g_x1);
        cudaGetSymbolAddress((void**)&p_z,   g_z);
        cudaGetSymbolAddress((void**)&p_hid, g_hid);
        cudaGetSymbolAddress((void**)&p_ye,  g_ye);
        cudaFuncSetAttribute(attn_kernel,
                             cudaFuncAttributeMaxDynamicSharedMemorySize, ATTN_SMEM);
        cudaFuncSetAttribute(gemm_3xtf32<true, false, false, 0>,
                             cudaFuncAttributeMaxDynamicSharedMemorySize, GEMM_SMEM);
        cudaFuncSetAttribute(gemm_3xtf32<true, false, true, 0>,
                             cudaFuncAttributeMaxDynamicSharedMemorySize, GEMM_SMEM);
        cudaFuncSetAttribute(gemm_3xtf32<true, true, false, 1>,
                             cudaFuncAttributeMaxDynamicSharedMemorySize, GEMM_SMEM);
        cudaFuncSetAttribute(gemm_3xtf32<false, false, false, 2>,
                             cudaFuncAttributeMaxDynamicSharedMemorySize, GEMM_SMEM);
        inited = true;
    }

    // 1. LN1
    ln_kernel<<<NTOK, 256>>>(x, ln1_g, ln1_b, p_h);
    // 2. QKV GEMM [8192,768]x[768,2304] (3xTF32 tensor cores)
    gemm_3xtf32<true, false, false, 0><<<dim3(C3 / 128, NTOK / 128), 256, GEMM_SMEM>>>(
        p_h, Wqkv, bqkv, nullptr, p_qkv, C3, CDIM);
    // 3. flash attention
    attn_kernel<<<dim3(TSEQ / 64, NH, 4), 256, ATTN_SMEM>>>(p_qkv, p_y);
    // 4. proj + residual
    gemm_3xtf32<true, false, true, 0><<<dim3(CDIM / 128, NTOK / 128), 256, GEMM_SMEM>>>(
        p_y, Wproj, bproj, x, p_x1, CDIM, CDIM);
    // 5. LN2
    ln_kernel<<<NTOK, 256>>>(p_x1, ln2_g, ln2_b, p_z);
    // 6. routing
    zero_kernel<<<1, 32>>>();
    router_kernel<<<NTOK / 8, 256>>>(p_z, Wr, br);
    prefix_kernel<<<1, 1>>>();
    assign_kernel<<<NTOK / 256, 256>>>();
    // 7. MoE grouped GEMMs (sparse top-2, 3xTF32 tensor cores)
    gemm_3xtf32<true, true, false, 1><<<dim3(DFF / 128, NTOK / 128, NEXP), 256, GEMM_SMEM>>>(
        p_z, W1, b1, nullptr, p_hid, DFF, CDIM);
    gemm_3xtf32<false, false, false, 2><<<dim3(CDIM / 128, NTOK / 128, NEXP), 256, GEMM_SMEM>>>(
        p_hid, W2, nullptr, nullptr, p_ye, CDIM, DFF);
    // 8. weighted gather + residual
    final_kernel<<<(NTOK * CDIM / 4 + 255) / 256, 256>>>(b2, out);
}

// round 11
// speedup vs baseline: 1.5381x; 1.2543x over previous
#include <cuda_runtime.h>
#include <cuda_fp16.h>
#include <cstdint>

#define NTOK  8192
#define CDIM  768
#define C3    2304
#define DFF   3072
#define NSLOT 16384
#define NEXP  8
#define TSEQ  2048
#define NH    12
#define HD    64

// ---------------- scratch (static device globals; no allocations) ----------------
__device__ float g_h  [NTOK * CDIM];
__device__ float g_qkv[(size_t)NTOK * C3];
__device__ float g_y  [NTOK * CDIM];
__device__ float g_x1 [NTOK * CDIM];
__device__ float g_z  [NTOK * CDIM];
__device__ float g_hid[(size_t)NSLOT * DFF];
__device__ float g_ye [(size_t)NSLOT * CDIM];
__device__ float g_wgt[NTOK * 2];
__device__ int   g_eidx[NTOK * 2];
__device__ int   g_slot[NTOK * 2];
__device__ int   g_tok[NSLOT];
__device__ int   g_cnt[NEXP];
__device__ int   g_off[NEXP];
__device__ int   g_cur[NEXP];

// ---------------- fp16 helpers -----------------------------------------------------
__device__ __forceinline__ uint32_t packh(__half a, __half b) {
    return (uint32_t)__half_as_ushort(a) | ((uint32_t)__half_as_ushort(b) << 16);
}

// split float4 into hi/lo half pairs (double-half decomposition)
__device__ __forceinline__ void split4(float4 v, uint2& h, uint2& l) {
    __half h0 = __float2half_rn(v.x), h1 = __float2half_rn(v.y);
    __half h2 = __float2half_rn(v.z), h3 = __float2half_rn(v.w);
    __half l0 = __float2half_rn(v.x - __half2float(h0));
    __half l1 = __float2half_rn(v.y - __half2float(h1));
    __half l2 = __float2half_rn(v.z - __half2float(h2));
    __half l3 = __float2half_rn(v.w - __half2float(h3));
    h.x = packh(h0, h1); h.y = packh(h2, h3);
    l.x = packh(l0, l1); l.y = packh(l2, l3);
}

__device__ __forceinline__ void mma_f16(float* c, const uint32_t* a, const uint32_t* b) {
    asm volatile(
        "mma.sync.aligned.m16n8k16.row.col.f32.f16.f16.f32 "
        "{%0,%1,%2,%3}, {%4,%5,%6,%7}, {%8,%9}, {%0,%1,%2,%3};\n"
        : "+f"(c[0]), "+f"(c[1]), "+f"(c[2]), "+f"(c[3])
        : "r"(a[0]), "r"(a[1]), "r"(a[2]), "r"(a[3]),
          "r"(b[0]), "r"(b[1]));
}

__device__ __forceinline__ void ldx4(uint32_t* r, uint32_t addr) {
    asm volatile("ldmatrix.sync.aligned.m8n8.x4.shared.b16 {%0,%1,%2,%3}, [%4];\n"
                 : "=r"(r[0]), "=r"(r[1]), "=r"(r[2]), "=r"(r[3]) : "r"(addr));
}
__device__ __forceinline__ void ldx2t(uint32_t* r, uint32_t addr) {
    asm volatile("ldmatrix.sync.aligned.m8n8.x2.trans.shared.b16 {%0,%1}, [%2];\n"
                 : "=r"(r[0]), "=r"(r[1]) : "r"(addr));
}

// ---------------- LayerNorm --------------------------------------------------------
__global__ __launch_bounds__(256) void ln_kernel(
    const float* __restrict__ x, const float* __restrict__ gam,
    const float* __restrict__ bet, float* __restrict__ out)
{
    const int row = blockIdx.x;
    const float* xr = x + (size_t)row * CDIM;
    float vals[3];
    float s1 = 0.f, s2 = 0.f;
#pragma unroll
    for (int u = 0; u < 3; u++) {
        float v = xr[threadIdx.x + u * 256];
        vals[u] = v; s1 += v; s2 += v * v;
    }
#pragma unroll
    for (int off = 16; off; off >>= 1) {
        s1 += __shfl_xor_sync(0xffffffffu, s1, off);
        s2 += __shfl_xor_sync(0xffffffffu, s2, off);
    }
    __shared__ float red1[8], red2[8];
    __shared__ float m_sh, r_sh;
    const int wid = threadIdx.x >> 5, lane = threadIdx.x & 31;
    if (lane == 0) { red1[wid] = s1; red2[wid] = s2; }
    __syncthreads();
    if (threadIdx.x == 0) {
        float a = 0.f, b = 0.f;
#pragma unroll
        for (int w = 0; w < 8; w++) { a += red1[w]; b += red2[w]; }
        float mean = a / CDIM;
        float var  = b / CDIM - mean * mean;
        m_sh = mean; r_sh = rsqrtf(var + 1e-5f);
    }
    __syncthreads();
    const float mean = m_sh, rstd = r_sh;
    float* orow = out + (size_t)row * CDIM;
#pragma unroll
    for (int u = 0; u < 3; u++) {
        int c = threadIdx.x + u * 256;
        orow[c] = (vals[u] - mean) * rstd * gam[c] + bet[c];
    }
}

// ---------------- 3xFP16 tensor-core GEMM (double-half, fp32-accurate) -------------
// 128x128x32 CTA tile, 8 warps (2x4), warp tile 64x32 via m16n8k16 fp16 mma.
// SMEM holds hi/lo halfs; fragments via ldmatrix; D = AhBh + AhBl + AlBh.
// MODE 0: plain A[M,K].  MODE 1: MoE gather (A row = g_tok[...]).  MODE 2: MoE direct.
#define LDAH 40              // halfs per A row (32 data + 8 pad) -> 80B stride
#define LDBH 136             // halfs per B k-row (128 data + 8 pad) -> 272B stride
#define A_HALFS (128 * LDAH)
#define B_HALFS (32 * LDBH)
#define STAGE_H (2 * A_HALFS + 2 * B_HALFS)
#define GEMM_SMEM (2 * STAGE_H * 2)

template<bool BIAS, bool RELU, bool RESID, int MODE>
__global__ __launch_bounds__(256, 2) void gemm_3xf16(
    const float* __restrict__ A, const float* __restrict__ Bw,
    const float* __restrict__ bias, const float* __restrict__ resid,
    float* __restrict__ Cm, int N, int K)
{
    extern __shared__ __half smem[];

    int cnt = 0, base = 0;
    if (MODE) {
        const int e = blockIdx.z;
        cnt = g_cnt[e]; base = g_off[e];
        if ((int)blockIdx.y * 128 >= cnt) return;
        Bw += (size_t)e * K * N;
        if (BIAS) bias += (size_t)e * N;
    }
    const int tid = threadIdx.x;
    const int rowBase = blockIdx.y * 128;
    const int colBase = blockIdx.x * 128;

    // A loader: 2 threads per row, 4 float4 each
    const int am = tid >> 1;
    const int arow = rowBase + am;
    bool aValid = true;
    const float* Arow;
    if (MODE == 1) {
        aValid = (arow < cnt);
        int t = aValid ? g_tok[base + arow] : 0;
        Arow = A + (size_t)t * K;
    } else if (MODE == 2) {
        aValid = (arow < cnt);
        Arow = A + (size_t)(base + (aValid ? arow : 0)) * K;
    } else {
        Arow = A + (size_t)arow * K;
    }
    const int bk = tid >> 5;
    const int bf = tid & 31;
    const float* Bcol = Bw + colBase + bf * 4;

    const int lane = tid & 31, wid = tid >> 5;
    const int g  = lane >> 2;
    const int t4 = lane & 3;
    const int lane15 = lane & 15;
    const int warpM = (wid >> 2) * 64;
    const int warpN = (wid & 3) * 32;

    float c[4][4][4];
#pragma unroll
    for (int i = 0; i < 4; i++)
#pragma unroll
        for (int j = 0; j < 4; j++)
#pragma unroll
            for (int q = 0; q < 4; q++) c[i][j][q] = 0.f;

    auto produce = [&](int k0, __half* st) {
        __half* AsH = st;
        __half* AsL = st + A_HALFS;
        __half* BsH = st + 2 * A_HALFS;
        __half* BsL = BsH + B_HALFS;
#pragma unroll
        for (int u = 0; u < 4; u++) {
            int f4 = u * 2 + (tid & 1);
            float4 av = aValid ? *(const float4*)(Arow + k0 + f4 * 4)
                               : make_float4(0.f, 0.f, 0.f, 0.f);
            uint2 h, l;
            split4(av, h, l);
            *(uint2*)&AsH[am * LDAH + f4 * 4] = h;
            *(uint2*)&AsL[am * LDAH + f4 * 4] = l;
            int kk = bk + u * 8;
            float4 bv = *(const float4*)(Bcol + (size_t)(k0 + kk) * N);
            split4(bv, h, l);
            *(uint2*)&BsH[kk * LDBH + bf * 4] = h;
            *(uint2*)&BsL[kk * LDBH + bf * 4] = l;
        }
    };

    const uint32_t smemAddr = (uint32_t)__cvta_generic_to_shared(smem);
    const int nIters = K / 32;
    produce(0, smem);
    __syncthreads();

    for (int it = 0; it < nIters; it++) {
        const uint32_t st = smemAddr + (uint32_t)((it & 1) * STAGE_H * 2);
        if (it + 1 < nIters)
            produce((it + 1) * 32, smem + (size_t)((it + 1) & 1) * STAGE_H);

        // per-lane ldmatrix base addresses (bytes)
        const uint32_t aH = st + (uint32_t)(((warpM + lane15) * LDAH + (lane >> 4) * 8) * 2);
        const uint32_t aL = aH + A_HALFS * 2;
        const uint32_t bH = st + (uint32_t)(2 * A_HALFS * 2) +
                            (uint32_t)((lane15 * LDBH + warpN) * 2);
        const uint32_t bL = bH + B_HALFS * 2;

#pragma unroll
        for (int ks = 0; ks < 2; ks++) {
            const uint32_t aks = ks * 32;            // +16 halfs along k
            const uint32_t bks = ks * 16 * LDBH * 2; // +16 k-rows
            uint32_t bh[4][2], bl[4][2];
#pragma unroll
            for (int nt = 0; nt < 4; nt++) {
                ldx2t(bh[nt], bH + bks + nt * 16);
                ldx2t(bl[nt], bL + bks + nt * 16);
            }
#pragma unroll
            for (int mt = 0; mt < 4; mt++) {
                uint32_t ah[4], al[4];
                ldx4(ah, aH + aks + mt * 16 * LDAH * 2);
                ldx4(al, aL + aks + mt * 16 * LDAH * 2);
#pragma unroll
                for (int nt = 0; nt < 4; nt++) {
                    mma_f16(c[mt][nt], ah, bl[nt]);
                    mma_f16(c[mt][nt], al, bh[nt]);
                    mma_f16(c[mt][nt], ah, bh[nt]);
                }
            }
        }
        __syncthreads();
    }

    // epilogue (m16n8 d-frag layout: rows g/g+8, cols 2*t4, 2*t4+1)
#pragma unroll
    for (int mt = 0; mt < 4; mt++) {
        const int r0 = rowBase + warpM + mt * 16 + g;
#pragma unroll
        for (int h = 0; h < 2; h++) {
            const int r = r0 + h * 8;
            if (MODE && r >= cnt) continue;
            const size_t orow = MODE ? (size_t)(base + r) : (size_t)r;
            float* cp = Cm + orow * N;
            const float* rp = RESID ? resid + (size_t)r * N : nullptr;
#pragma unroll
            for (int nt = 0; nt < 4; nt++) {
                const int col = colBase + warpN + nt * 8 + 2 * t4;
                float v0 = c[mt][nt][h * 2 + 0];
                float v1 = c[mt][nt][h * 2 + 1];
                if (BIAS) { v0 += bias[col]; v1 += bias[col + 1]; }
                if (RESID) { v0 += rp[col]; v1 += rp[col + 1]; }
                if (RELU) { v0 = fmaxf(v0, 0.f); v1 = fmaxf(v1, 0.f); }
                float2 vv; vv.x = v0; vv.y = v1;
                *(float2*)(cp + col) = vv;
            }
        }
    }
}

// ---------------- flash attention: 64-row Q tiles, online softmax ------------------
#define ATTN_SMEM (4 * 64 * 65 * 4)
__global__ __launch_bounds__(256) void attn_kernel(
    const float* __restrict__ qkv, float* __restrict__ y)
{
    extern __shared__ float sm[];
    float* Qs = sm;
    float* Ks = Qs + 64 * 65;
    float* Vs = Ks + 64 * 65;
    float* Ps = Vs + 64 * 65;

    const int qt = blockIdx.x;
    const int h  = blockIdx.y;
    const int b  = blockIdx.z;
    const int tid = threadIdx.x;
    const int r  = tid >> 2;
    const int c0 = (tid & 3) * 16;

    const int qRow0 = qt * 64;
    const float* qbase = qkv + (size_t)b * TSEQ * C3 + h * HD;

#pragma unroll
    for (int u = 0; u < 4; u++) {
        int lin = tid + u * 256;
        int rr = lin >> 4;
        int cc = (lin & 15) * 4;
        float4 v4 = *(const float4*)(qbase + (size_t)(qRow0 + rr) * C3 + cc);
        Qs[rr * 65 + cc + 0] = v4.x; Qs[rr * 65 + cc + 1] = v4.y;
        Qs[rr * 65 + cc + 2] = v4.z; Qs[rr * 65 + cc + 3] = v4.w;
    }

    float o[16];
#pragma unroll
    for (int i = 0; i < 16; i++) o[i] = 0.f;
    float m = -1e30f, l = 0.f;
    const float scale = 0.125f;

    for (int j0 = 0; j0 <= qRow0; j0 += 64) {
        __syncthreads();
#pragma unroll
        for (int u = 0; u < 4; u++) {
            int lin = tid + u * 256;
            int rr = lin >> 4;
            int cc = (lin & 15) * 4;
            const float* kb = qbase + CDIM  + (size_t)(j0 + rr) * C3 + cc;
            const float* vb = qbase + 2*CDIM + (size_t)(j0 + rr) * C3 + cc;
            float4 k4 = *(const float4*)kb;
            float4 v4 = *(const float4*)vb;
            Ks[rr * 65 + cc + 0] = k4.x; Ks[rr * 65 + cc + 1] = k4.y;
            Ks[rr * 65 + cc + 2] = k4.z; Ks[rr * 65 + cc + 3] = k4.w;
            Vs[rr * 65 + cc + 0] = v4.x; Vs[rr * 65 + cc + 1] = v4.y;
            Vs[rr * 65 + cc + 2] = v4.z; Vs[rr * 65 + cc + 3] = v4.w;
        }
        __syncthreads();

        float s[16];
#pragma unroll
        for (int i = 0; i < 16; i++) s[i] = 0.f;
        for (int d = 0; d < 64; d++) {
            float qv = Qs[r * 65 + d];
#pragma unroll
            for (int i = 0; i < 16; i++) s[i] += qv * Ks[(c0 + i) * 65 + d];
        }
        const int qg = qRow0 + r;
        float mloc = -1e30f;
#pragma unroll
        for (int i = 0; i < 16; i++) {
            int kg = j0 + c0 + i;
            s[i] = (kg <= qg) ? s[i] * scale : -1e30f;
            mloc = fmaxf(mloc, s[i]);
        }
        mloc = fmaxf(mloc, __shfl_xor_sync(0xffffffffu, mloc, 1));
        mloc = fmaxf(mloc, __shfl_xor_sync(0xffffffffu, mloc, 2));
        float mnew = fmaxf(m, mloc);
        float alpha = __expf(m - mnew);
        float ssum = 0.f;
#pragma unroll
        for (int i = 0; i < 16; i++) {
            float p = __expf(s[i] - mnew);
            Ps[r * 65 + c0 + i] = p;
            ssum += p;
        }
        ssum += __shfl_xor_sync(0xffffffffu, ssum, 1);
        ssum += __shfl_xor_sync(0xffffffffu, ssum, 2);
        l = l * alpha + ssum;
        m = mnew;
#pragma unroll
        for (int i = 0; i < 16; i++) o[i] *= alpha;
        __syncthreads();
        for (int kk = 0; kk < 64; kk++) {
            float p = Ps[r * 65 + kk];
#pragma unroll
            for (int i = 0; i < 16; i++) o[i] += p * Vs[kk * 65 + c0 + i];
        }
    }

    const float inv = 1.f / l;
    float* yb = y + (size_t)(b * TSEQ + qRow0 + r) * CDIM + h * HD + c0;
#pragma unroll
    for (int i = 0; i < 16; i++) yb[i] = o[i] * inv;
}

// ---------------- router -----------------------------------------------------------
__global__ __launch_bounds__(256) void router_kernel(
    const float* __restrict__ z, const float* __restrict__ Wr,
    const float* __restrict__ br)
{
    const int warp = (blockIdx.x * blockDim.x + threadIdx.x) >> 5;
    const int lane = threadIdx.x & 31;
    if (warp >= NTOK) return;
    const float* zr = z + (size_t)warp * CDIM;
    float p[NEXP];
#pragma unroll
    for (int e = 0; e < NEXP; e++) p[e] = 0.f;
    for (int c = lane; c < CDIM; c += 32) {
        float zv = zr[c];
        const float* wrow = Wr + c * NEXP;
#pragma unroll
        for (int e = 0; e < NEXP; e++) p[e] += zv * wrow[e];
    }
#pragma unroll
    for (int off = 16; off; off >>= 1)
#pragma unroll
        for (int e = 0; e < NEXP; e++) p[e] += __shfl_xor_sync(0xffffffffu, p[e], off);
    if (lane == 0) {
        float lg[NEXP];
#pragma unroll
        for (int e = 0; e < NEXP; e++) lg[e] = p[e] + br[e];
        int e0 = 0;
#pragma unroll
        for (int e = 1; e < NEXP; e++) if (lg[e] > lg[e0]) e0 = e;
        int e1 = (e0 == 0) ? 1 : 0;
#pragma unroll
        for (int e = 0; e < NEXP; e++) if (e != e0 && lg[e] > lg[e1]) e1 = e;
        float w0 = 1.f / (1.f + __expf(lg[e1] - lg[e0]));
        g_wgt[warp * 2] = w0;
        g_wgt[warp * 2 + 1] = 1.f - w0;
        g_eidx[warp * 2] = e0;
        g_eidx[warp * 2 + 1] = e1;
        atomicAdd(&g_cnt[e0], 1);
        atomicAdd(&g_cnt[e1], 1);
    }
}

__global__ void zero_kernel() {
    int t = threadIdx.x;
    if (t < NEXP) { g_cnt[t] = 0; g_cur[t] = 0; }
}

__global__ void prefix_kernel() {
    int s = 0;
    for (int e = 0; e < NEXP; e++) { g_off[e] = s; s += g_cnt[e]; }
}

__global__ __launch_bounds__(256) void assign_kernel() {
    int n = blockIdx.x * blockDim.x + threadIdx.x;
    if (n >= NTOK) return;
#pragma unroll
    for (int k = 0; k < 2; k++) {
        int e = g_eidx[n * 2 + k];
        int pos = atomicAdd(&g_cur[e], 1);
        int slot = g_off[e] + pos;
        g_slot[n * 2 + k] = slot;
        g_tok[slot] = n;
    }
}

// ---------------- final: out = x1 + sum_k w_k * (ye_k + b2[e_k]) -------------------
__global__ __launch_bounds__(256) void final_kernel(
    const float* __restrict__ b2, float* __restrict__ out)
{
    int i = blockIdx.x * blockDim.x + threadIdx.x;
    const int total = NTOK * CDIM / 4;
    if (i >= total) return;
    int n = i / (CDIM / 4);
    int c = (i % (CDIM / 4)) * 4;
    float w0 = g_wgt[n * 2], w1 = g_wgt[n * 2 + 1];
    int e0 = g_eidx[n * 2], e1 = g_eidx[n * 2 + 1];
    int s0 = g_slot[n * 2], s1 = g_slot[n * 2 + 1];
    float4 xv  = *(const float4*)&g_x1[(size_t)n * CDIM + c];
    float4 y0  = *(const float4*)&g_ye[(size_t)s0 * CDIM + c];
    float4 y1  = *(const float4*)&g_ye[(size_t)s1 * CDIM + c];
    float4 b0  = *(const float4*)&b2[(size_t)e0 * CDIM + c];
    float4 b1v = *(const float4*)&b2[(size_t)e1 * CDIM + c];
    float4 r;
    r.x = xv.x + w0 * (y0.x + b0.x) + w1 * (y1.x + b1v.x);
    r.y = xv.y + w0 * (y0.y + b0.y) + w1 * (y1.y + b1v.y);
    r.z = xv.z + w0 * (y0.z + b0.z) + w1 * (y1.z + b1v.z);
    r.w = xv.w + w0 * (y0.w + b0.w) + w1 * (y1.w + b1v.w);
    *(float4*)&out[(size_t)n * CDIM + c] = r;
}

// ---------------- launch -----------------------------------------------------------
extern "C" void kernel_launch(void* const* d_in, const int* in_sizes, int n_in,
                              void* d_out, int out_size)
{
    const float* x      = (const float*)d_in[0];
    const float* ln1_g  = (const float*)d_in[1];
    const float* ln1_b  = (const float*)d_in[2];
    const float* Wqkv   = (const float*)d_in[3];
    const float* bqkv   = (const float*)d_in[4];
    const float* Wproj  = (const float*)d_in[5];
    const float* bproj  = (const float*)d_in[6];
    const float* ln2_g  = (const float*)d_in[7];
    const float* ln2_b  = (const float*)d_in[8];
    const float* Wr     = (const float*)d_in[9];
    const float* br     = (const float*)d_in[10];
    const float* W1     = (const float*)d_in[11];
    const float* b1     = (const float*)d_in[12];
    const float* W2     = (const float*)d_in[13];
    const float* b2     = (const float*)d_in[14];
    float* out = (float*)d_out;

    static bool inited = false;
    static float *p_h, *p_qkv, *p_y, *p_x1, *p_z, *p_hid, *p_ye;
    if (!inited) {
        cudaGetSymbolAddress((void**)&p_h,   g_h);
        cudaGetSymbolAddress((void**)&p_qkv, g_qkv);
        cudaGetSymbolAddress((void**)&p_y,   g_y);
        cudaGetSymbolAddress((void**)&p_x1,  g_x1);
        cudaGetSymbolAddress((void**)&p_z,   g_z);
        cudaGetSymbolAddress((void**)&p_hid, g_hid);
        cudaGetSymbolAddress((void**)&p_ye,  g_ye);
        cudaFuncSetAttribute(attn_kernel,
                             cudaFuncAttributeMaxDynamicSharedMemorySize, ATTN_SMEM);
        cudaFuncSetAttribute(gemm_3xf16<true, false, false, 0>,
                             cudaFuncAttributeMaxDynamicSharedMemorySize, GEMM_SMEM);
        cudaFuncSetAttribute(gemm_3xf16<true, false, true, 0>,
                             cudaFuncAttributeMaxDynamicSharedMemorySize, GEMM_SMEM);
        cudaFuncSetAttribute(gemm_3xf16<true, true, false, 1>,
                             cudaFuncAttributeMaxDynamicSharedMemorySize, GEMM_SMEM);
        cudaFuncSetAttribute(gemm_3xf16<false, false, false, 2>,
                             cudaFuncAttributeMaxDynamicSharedMemorySize, GEMM_SMEM);
        inited = true;
    }

    // 1. LN1
    ln_kernel<<<NTOK, 256>>>(x, ln1_g, ln1_b, p_h);
    // 2. QKV GEMM [8192,768]x[768,2304] (3xFP16 tensor cores)
    gemm_3xf16<true, false, false, 0><<<dim3(C3 / 128, NTOK / 128), 256, GEMM_SMEM>>>(
        p_h, Wqkv, bqkv, nullptr, p_qkv, C3, CDIM);
    // 3. flash attention
    attn_kernel<<<dim3(TSEQ / 64, NH, 4), 256, ATTN_SMEM>>>(p_qkv, p_y);
    // 4. proj + residual
    gemm_3xf16<true, false, true, 0><<<dim3(CDIM / 128, NTOK / 128), 256, GEMM_SMEM>>>(
        p_y, Wproj, bproj, x, p_x1, CDIM, CDIM);
    // 5. LN2
    ln_kernel<<<NTOK, 256>>>(p_x1, ln2_g, ln2_b, p_z);
    // 6. routing
    zero_kernel<<<1, 32>>>();
    router_kernel<<<NTOK / 8, 256>>>(p_z, Wr, br);
    prefix_kernel<<<1, 1>>>();
    assign_kernel<<<NTOK / 256, 256>>>();
    // 7. MoE grouped GEMMs (sparse top-2, 3xFP16 tensor cores)
    gemm_3xf16<true, true, false, 1><<<dim3(DFF / 128, NTOK / 128, NEXP), 256, GEMM_SMEM>>>(
        p_z, W1, b1, nullptr, p_hid, DFF, CDIM);
    gemm_3xf16<false, false, false, 2><<<dim3(CDIM / 128, NTOK / 128, NEXP), 256, GEMM_SMEM>>>(
        p_hid, W2, nullptr, nullptr, p_ye, CDIM, DFF);
    // 8. weighted gather + residual
    final_kernel<<<(NTOK * CDIM / 4 + 255) / 256, 256>>>(b2, out);
}

// round 14
// speedup vs baseline: 3.4463x; 2.2406x over previous
#include <cuda_runtime.h>
#include <cuda_fp16.h>
#include <cstdint>

#define NTOK  8192
#define CDIM  768
#define C3    2304
#define DFF   3072
#define NSLOT 16384
#define NEXP  8
#define TSEQ  2048
#define NH    12
#define HD    64

// ---------------- scratch (static device globals; no allocations) ----------------
__device__ float g_h  [NTOK * CDIM];
__device__ float g_qkv[(size_t)NTOK * C3];
__device__ float g_y  [NTOK * CDIM];
__device__ float g_x1 [NTOK * CDIM];
__device__ float g_z  [NTOK * CDIM];
__device__ float g_hid[(size_t)NSLOT * DFF];
__device__ float g_ye [(size_t)NSLOT * CDIM];
__device__ float g_wgt[NTOK * 2];
__device__ int   g_eidx[NTOK * 2];
__device__ int   g_slot[NTOK * 2];
__device__ int   g_tok[NSLOT];
__device__ int   g_cnt[NEXP];
__device__ int   g_off[NEXP];
__device__ int   g_cur[NEXP];

// ---------------- fp16 helpers -----------------------------------------------------
__device__ __forceinline__ uint32_t packh(__half a, __half b) {
    return (uint32_t)__half_as_ushort(a) | ((uint32_t)__half_as_ushort(b) << 16);
}

__device__ __forceinline__ void split4(float4 v, uint2& h, uint2& l) {
    __half h0 = __float2half_rn(v.x), h1 = __float2half_rn(v.y);
    __half h2 = __float2half_rn(v.z), h3 = __float2half_rn(v.w);
    __half l0 = __float2half_rn(v.x - __half2float(h0));
    __half l1 = __float2half_rn(v.y - __half2float(h1));
    __half l2 = __float2half_rn(v.z - __half2float(h2));
    __half l3 = __float2half_rn(v.w - __half2float(h3));
    h.x = packh(h0, h1); h.y = packh(h2, h3);
    l.x = packh(l0, l1); l.y = packh(l2, l3);
}

__device__ __forceinline__ void mma_f16(float* c, const uint32_t* a, const uint32_t* b) {
    asm volatile(
        "mma.sync.aligned.m16n8k16.row.col.f32.f16.f16.f32 "
        "{%0,%1,%2,%3}, {%4,%5,%6,%7}, {%8,%9}, {%0,%1,%2,%3};\n"
        : "+f"(c[0]), "+f"(c[1]), "+f"(c[2]), "+f"(c[3])
        : "r"(a[0]), "r"(a[1]), "r"(a[2]), "r"(a[3]),
          "r"(b[0]), "r"(b[1]));
}

__device__ __forceinline__ void ldx4(uint32_t* r, uint32_t addr) {
    asm volatile("ldmatrix.sync.aligned.m8n8.x4.shared.b16 {%0,%1,%2,%3}, [%4];\n"
                 : "=r"(r[0]), "=r"(r[1]), "=r"(r[2]), "=r"(r[3]) : "r"(addr));
}
__device__ __forceinline__ void ldx2(uint32_t* r, uint32_t addr) {
    asm volatile("ldmatrix.sync.aligned.m8n8.x2.shared.b16 {%0,%1}, [%2];\n"
                 : "=r"(r[0]), "=r"(r[1]) : "r"(addr));
}
__device__ __forceinline__ void ldx2t(uint32_t* r, uint32_t addr) {
    asm volatile("ldmatrix.sync.aligned.m8n8.x2.trans.shared.b16 {%0,%1}, [%2];\n"
                 : "=r"(r[0]), "=r"(r[1]) : "r"(addr));
}

// ---------------- LayerNorm --------------------------------------------------------
__global__ __launch_bounds__(256) void ln_kernel(
    const float* __restrict__ x, const float* __restrict__ gam,
    const float* __restrict__ bet, float* __restrict__ out)
{
    const int row = blockIdx.x;
    const float* xr = x + (size_t)row * CDIM;
    float vals[3];
    float s1 = 0.f, s2 = 0.f;
#pragma unroll
    for (int u = 0; u < 3; u++) {
        float v = xr[threadIdx.x + u * 256];
        vals[u] = v; s1 += v; s2 += v * v;
    }
#pragma unroll
    for (int off = 16; off; off >>= 1) {
        s1 += __shfl_xor_sync(0xffffffffu, s1, off);
        s2 += __shfl_xor_sync(0xffffffffu, s2, off);
    }
    __shared__ float red1[8], red2[8];
    __shared__ float m_sh, r_sh;
    const int wid = threadIdx.x >> 5, lane = threadIdx.x & 31;
    if (lane == 0) { red1[wid] = s1; red2[wid] = s2; }
    __syncthreads();
    if (threadIdx.x == 0) {
        float a = 0.f, b = 0.f;
#pragma unroll
        for (int w = 0; w < 8; w++) { a += red1[w]; b += red2[w]; }
        float mean = a / CDIM;
        float var  = b / CDIM - mean * mean;
        m_sh = mean; r_sh = rsqrtf(var + 1e-5f);
    }
    __syncthreads();
    const float mean = m_sh, rstd = r_sh;
    float* orow = out + (size_t)row * CDIM;
#pragma unroll
    for (int u = 0; u < 3; u++) {
        int c = threadIdx.x + u * 256;
        orow[c] = (vals[u] - mean) * rstd * gam[c] + bet[c];
    }
}

// ---------------- 3xFP16 tensor-core GEMM (double-half, fp32-accurate) -------------
#define LDAH 40
#define LDBH 136
#define A_HALFS (128 * LDAH)
#define B_HALFS (32 * LDBH)
#define STAGE_H (2 * A_HALFS + 2 * B_HALFS)
#define GEMM_SMEM (2 * STAGE_H * 2)

template<bool BIAS, bool RELU, bool RESID, int MODE>
__global__ __launch_bounds__(256, 2) void gemm_3xf16(
    const float* __restrict__ A, const float* __restrict__ Bw,
    const float* __restrict__ bias, const float* __restrict__ resid,
    float* __restrict__ Cm, int N, int K)
{
    extern __shared__ __half smem[];

    int cnt = 0, base = 0;
    if (MODE) {
        const int e = blockIdx.z;
        cnt = g_cnt[e]; base = g_off[e];
        if ((int)blockIdx.y * 128 >= cnt) return;
        Bw += (size_t)e * K * N;
        if (BIAS) bias += (size_t)e * N;
    }
    const int tid = threadIdx.x;
    const int rowBase = blockIdx.y * 128;
    const int colBase = blockIdx.x * 128;

    const int am = tid >> 1;
    const int arow = rowBase + am;
    bool aValid = true;
    const float* Arow;
    if (MODE == 1) {
        aValid = (arow < cnt);
        int t = aValid ? g_tok[base + arow] : 0;
        Arow = A + (size_t)t * K;
    } else if (MODE == 2) {
        aValid = (arow < cnt);
        Arow = A + (size_t)(base + (aValid ? arow : 0)) * K;
    } else {
        Arow = A + (size_t)arow * K;
    }
    const int bk = tid >> 5;
    const int bf = tid & 31;
    const float* Bcol = Bw + colBase + bf * 4;

    const int lane = tid & 31, wid = tid >> 5;
    const int g  = lane >> 2;
    const int t4 = lane & 3;
    const int lane15 = lane & 15;
    const int warpM = (wid >> 2) * 64;
    const int warpN = (wid & 3) * 32;

    float c[4][4][4];
#pragma unroll
    for (int i = 0; i < 4; i++)
#pragma unroll
        for (int j = 0; j < 4; j++)
#pragma unroll
            for (int q = 0; q < 4; q++) c[i][j][q] = 0.f;

    auto produce = [&](int k0, __half* st) {
        __half* AsH = st;
        __half* AsL = st + A_HALFS;
        __half* BsH = st + 2 * A_HALFS;
        __half* BsL = BsH + B_HALFS;
#pragma unroll
        for (int u = 0; u < 4; u++) {
            int f4 = u * 2 + (tid & 1);
            float4 av = aValid ? *(const float4*)(Arow + k0 + f4 * 4)
                               : make_float4(0.f, 0.f, 0.f, 0.f);
            uint2 hh, ll;
            split4(av, hh, ll);
            *(uint2*)&AsH[am * LDAH + f4 * 4] = hh;
            *(uint2*)&AsL[am * LDAH + f4 * 4] = ll;
            int kk = bk + u * 8;
            float4 bv = *(const float4*)(Bcol + (size_t)(k0 + kk) * N);
            split4(bv, hh, ll);
            *(uint2*)&BsH[kk * LDBH + bf * 4] = hh;
            *(uint2*)&BsL[kk * LDBH + bf * 4] = ll;
        }
    };

    const uint32_t smemAddr = (uint32_t)__cvta_generic_to_shared(smem);
    const int nIters = K / 32;
    produce(0, smem);
    __syncthreads();

    for (int it = 0; it < nIters; it++) {
        const uint32_t st = smemAddr + (uint32_t)((it & 1) * STAGE_H * 2);
        if (it + 1 < nIters)
            produce((it + 1) * 32, smem + (size_t)((it + 1) & 1) * STAGE_H);

        const uint32_t aH = st + (uint32_t)(((warpM + lane15) * LDAH + (lane >> 4) * 8) * 2);
        const uint32_t aL = aH + A_HALFS * 2;
        const uint32_t bH = st + (uint32_t)(2 * A_HALFS * 2) +
                            (uint32_t)((lane15 * LDBH + warpN) * 2);
        const uint32_t bL = bH + B_HALFS * 2;

#pragma unroll
        for (int ks = 0; ks < 2; ks++) {
            const uint32_t aks = ks * 32;
            const uint32_t bks = ks * 16 * LDBH * 2;
            uint32_t bh[4][2], bl[4][2];
#pragma unroll
            for (int nt = 0; nt < 4; nt++) {
                ldx2t(bh[nt], bH + bks + nt * 16);
                ldx2t(bl[nt], bL + bks + nt * 16);
            }
#pragma unroll
            for (int mt = 0; mt < 4; mt++) {
                uint32_t ah[4], al[4];
                ldx4(ah, aH + aks + mt * 16 * LDAH * 2);
                ldx4(al, aL + aks + mt * 16 * LDAH * 2);
#pragma unroll
                for (int nt = 0; nt < 4; nt++) {
                    mma_f16(c[mt][nt], ah, bl[nt]);
                    mma_f16(c[mt][nt], al, bh[nt]);
                    mma_f16(c[mt][nt], ah, bh[nt]);
                }
            }
        }
        __syncthreads();
    }

#pragma unroll
    for (int mt = 0; mt < 4; mt++) {
        const int r0 = rowBase + warpM + mt * 16 + g;
#pragma unroll
        for (int hh = 0; hh < 2; hh++) {
            const int r = r0 + hh * 8;
            if (MODE && r >= cnt) continue;
            const size_t orow = MODE ? (size_t)(base + r) : (size_t)r;
            float* cp = Cm + orow * N;
            const float* rp = RESID ? resid + (size_t)r * N : nullptr;
#pragma unroll
            for (int nt = 0; nt < 4; nt++) {
                const int col = colBase + warpN + nt * 8 + 2 * t4;
                float v0 = c[mt][nt][hh * 2 + 0];
                float v1 = c[mt][nt][hh * 2 + 1];
                if (BIAS) { v0 += bias[col]; v1 += bias[col + 1]; }
                if (RESID) { v0 += rp[col]; v1 += rp[col + 1]; }
                if (RELU) { v0 = fmaxf(v0, 0.f); v1 = fmaxf(v1, 0.f); }
                float2 vv; vv.x = v0; vv.y = v1;
                *(float2*)(cp + col) = vv;
            }
        }
    }
}

// ---------------- 3xFP16 flash attention -------------------------------------------
// 128-row Q tile per CTA (8 warps). Warp w owns rows {8w..8w+7} U {64+8w..64+8w+7}
// as the two m8 halves of its m16 fragment (causal load balance).
// S = QK^T and O = P*V both via 3-term double-half mma. Softmax fp32 in registers.
#define ASTR 72                   // smem row stride in halfs (144B -> conflict-free)
#define ATTN_KH 0
#define ATTN_KL (64 * ASTR)
#define ATTN_VH (2 * 64 * ASTR)
#define ATTN_VL (3 * 64 * ASTR)
#define ATTN_SMEM2 (4 * 64 * ASTR * 2)   // 36864 bytes (also fits Q phase 128*ASTR*2)

__global__ __launch_bounds__(256) void attn_mma(
    const float* __restrict__ qkv, float* __restrict__ y)
{
    extern __shared__ __half sm[];
    const int qt = blockIdx.x;          // 16 tiles of 128 rows
    const int hd = blockIdx.y;          // head
    const int b  = blockIdx.z;
    const int tid  = threadIdx.x;
    const int lane = tid & 31;
    const int w    = tid >> 5;
    const int g    = lane >> 2;
    const int t4   = lane & 3;
    const int lane15 = lane & 15;
    const int qRow0 = qt * 128;
    const float* qbase = qkv + (size_t)b * TSEQ * C3 + hd * HD;
    const uint32_t smb = (uint32_t)__cvta_generic_to_shared(sm);

    // ---- phase 1: Q tile 128x64 -> hi/lo smem, then frags
    #pragma unroll
    for (int u = 0; u < 8; u++) {
        int lin = tid + u * 256;        // 2048 float4
        int r = lin >> 4, c4 = (lin & 15) * 4;
        float4 v = *(const float4*)(qbase + (size_t)(qRow0 + r) * C3 + c4);
        uint2 hh, ll;
        split4(v, hh, ll);
        *(uint2*)&sm[r * ASTR + c4] = hh;
        *(uint2*)&sm[128 * ASTR + r * ASTR + c4] = ll;
    }
    __syncthreads();

    uint32_t qh[4][4], ql[4][4];
    {
        int row = (lane15 < 8) ? (8 * w + lane15) : (64 + 8 * w + lane15 - 8);
        uint32_t base = smb + (uint32_t)((row * ASTR + (lane >> 4) * 8) * 2);
        #pragma unroll
        for (int ks = 0; ks < 4; ks++) {
            ldx4(qh[ks], base + ks * 32);
            ldx4(ql[ks], base + ks * 32 + 128 * ASTR * 2);
        }
    }
    __syncthreads();   // Q smem can now be overwritten by K/V

    float o[8][4];
    #pragma unroll
    for (int i = 0; i < 8; i++)
        #pragma unroll
        for (int j = 0; j < 4; j++) o[i][j] = 0.f;
    float m0 = -1e30f, m1 = -1e30f, l0 = 0.f, l1 = 0.f;
    const int row0 = qRow0 + 8 * w + g;
    const int row1 = row0 + 64;
    const int row1max = qRow0 + 64 + 8 * w + 7;
    const float scale = 0.125f;
    const int nTiles = qt * 2 + 2;

    for (int t = 0; t < nTiles; t++) {
        const int j0 = t * 64;
        // ---- load K/V tile 64x64 fp32 each -> hi/lo halfs
        #pragma unroll
        for (int u = 0; u < 4; u++) {
            int lin = tid + u * 256;    // 1024 float4 per matrix
            int r = lin >> 4, c4 = (lin & 15) * 4;
            float4 kv = *(const float4*)(qbase + CDIM + (size_t)(j0 + r) * C3 + c4);
            uint2 hh, ll;
            split4(kv, hh, ll);
            *(uint2*)&sm[ATTN_KH + r * ASTR + c4] = hh;
            *(uint2*)&sm[ATTN_KL + r * ASTR + c4] = ll;
            float4 vv = *(const float4*)(qbase + 2 * CDIM + (size_t)(j0 + r) * C3 + c4);
            split4(vv, hh, ll);
            *(uint2*)&sm[ATTN_VH + r * ASTR + c4] = hh;
            *(uint2*)&sm[ATTN_VL + r * ASTR + c4] = ll;
        }
        __syncthreads();

        if (j0 <= row1max) {
            // ---- S = Q K^T (3-term)
            float s[8][4];
            #pragma unroll
            for (int i = 0; i < 8; i++)
                #pragma unroll
                for (int j = 0; j < 4; j++) s[i][j] = 0.f;
            {
                const uint32_t kb = smb + (uint32_t)((((lane15 & 7) * ASTR) + (lane15 >> 3) * 8) * 2);
                #pragma unroll
                for (int nt = 0; nt < 8; nt++) {
                    const uint32_t knt = kb + (uint32_t)(nt * 8 * ASTR * 2);
                    #pragma unroll
                    for (int ks = 0; ks < 4; ks++) {
                        uint32_t kh2[2], kl2[2];
                        ldx2(kh2, knt + ks * 32 + ATTN_KH * 2);
                        ldx2(kl2, knt + ks * 32 + ATTN_KL * 2);
                        mma_f16(s[nt], qh[ks], kl2);
                        mma_f16(s[nt], ql[ks], kh2);
                        mma_f16(s[nt], qh[ks], kh2);
                    }
                }
            }
            // ---- mask + online softmax
            float mloc0 = -1e30f, mloc1 = -1e30f;
            #pragma unroll
            for (int nt = 0; nt < 8; nt++) {
                int kg = j0 + nt * 8 + 2 * t4;
                s[nt][0] = (kg     <= row0) ? s[nt][0] * scale : -1e30f;
                s[nt][1] = (kg + 1 <= row0) ? s[nt][1] * scale : -1e30f;
                s[nt][2] = (kg     <= row1) ? s[nt][2] * scale : -1e30f;
                s[nt][3] = (kg + 1 <= row1) ? s[nt][3] * scale : -1e30f;
                mloc0 = fmaxf(mloc0, fmaxf(s[nt][0], s[nt][1]));
                mloc1 = fmaxf(mloc1, fmaxf(s[nt][2], s[nt][3]));
            }
            mloc0 = fmaxf(mloc0, __shfl_xor_sync(0xffffffffu, mloc0, 1));
            mloc0 = fmaxf(mloc0, __shfl_xor_sync(0xffffffffu, mloc0, 2));
            mloc1 = fmaxf(mloc1, __shfl_xor_sync(0xffffffffu, mloc1, 1));
            mloc1 = fmaxf(mloc1, __shfl_xor_sync(0xffffffffu, mloc1, 2));
            float mn0 = fmaxf(m0, mloc0), mn1 = fmaxf(m1, mloc1);
            float a0 = __expf(m0 - mn0), a1 = __expf(m1 - mn1);
            float ls0 = 0.f, ls1 = 0.f;
            #pragma unroll
            for (int nt = 0; nt < 8; nt++) {
                s[nt][0] = __expf(s[nt][0] - mn0);
                s[nt][1] = __expf(s[nt][1] - mn0);
                s[nt][2] = __expf(s[nt][2] - mn1);
                s[nt][3] = __expf(s[nt][3] - mn1);
                ls0 += s[nt][0] + s[nt][1];
                ls1 += s[nt][2] + s[nt][3];
            }
            ls0 += __shfl_xor_sync(0xffffffffu, ls0, 1);
            ls0 += __shfl_xor_sync(0xffffffffu, ls0, 2);
            ls1 += __shfl_xor_sync(0xffffffffu, ls1, 1);
            ls1 += __shfl_xor_sync(0xffffffffu, ls1, 2);
            l0 = l0 * a0 + ls0;  l1 = l1 * a1 + ls1;
            m0 = mn0;  m1 = mn1;
            #pragma unroll
            for (int dt = 0; dt < 8; dt++) {
                o[dt][0] *= a0; o[dt][1] *= a0;
                o[dt][2] *= a1; o[dt][3] *= a1;
            }
            // ---- O += P V (3-term)
            const uint32_t vb = smb + (uint32_t)((lane15 * ASTR) * 2);
            #pragma unroll
            for (int ks = 0; ks < 4; ks++) {
                uint32_t ph[4], pl[4];
                #pragma unroll
                for (int half16 = 0; half16 < 2; half16++) {
                    int nt = ks * 2 + half16;
                    __half h0 = __float2half_rn(s[nt][0]);
                    __half h1 = __float2half_rn(s[nt][1]);
                    __half h2 = __float2half_rn(s[nt][2]);
                    __half h3 = __float2half_rn(s[nt][3]);
                    ph[half16 * 2 + 0] = packh(h0, h1);
                    ph[half16 * 2 + 1] = packh(h2, h3);
                    pl[half16 * 2 + 0] = packh(
                        __float2half_rn(s[nt][0] - __half2float(h0)),
                        __float2half_rn(s[nt][1] - __half2float(h1)));
                    pl[half16 * 2 + 1] = packh(
                        __float2half_rn(s[nt][2] - __half2float(h2)),
                        __float2half_rn(s[nt][3] - __half2float(h3)));
                }
                uint32_t pha[4] = { ph[0], ph[1], ph[2], ph[3] };
                uint32_t pla[4] = { pl[0], pl[1], pl[2], pl[3] };
                const uint32_t vks = vb + (uint32_t)(ks * 16 * ASTR * 2);
                #pragma unroll
                for (int dt = 0; dt < 8; dt++) {
                    uint32_t vh2[2], vl2[2];
                    ldx2t(vh2, vks + dt * 16 + ATTN_VH * 2);
                    ldx2t(vl2, vks + dt * 16 + ATTN_VL * 2);
                    mma_f16(o[dt], pha, vl2);
                    mma_f16(o[dt], pla, vh2);
                    mma_f16(o[dt], pha, vh2);
                }
            }
        }
        __syncthreads();
    }

    // ---- epilogue
    const float inv0 = 1.f / l0, inv1 = 1.f / l1;
    float* y0 = y + (size_t)(b * TSEQ + row0) * CDIM + hd * HD;
    float* y1 = y + (size_t)(b * TSEQ + row1) * CDIM + hd * HD;
    #pragma unroll
    for (int dt = 0; dt < 8; dt++) {
        int col = dt * 8 + 2 * t4;
        float2 v0; v0.x = o[dt][0] * inv0; v0.y = o[dt][1] * inv0;
        float2 v1; v1.x = o[dt][2] * inv1; v1.y = o[dt][3] * inv1;
        *(float2*)(y0 + col) = v0;
        *(float2*)(y1 + col) = v1;
    }
}

// ---------------- router -----------------------------------------------------------
__global__ __launch_bounds__(256) void router_kernel(
    const float* __restrict__ z, const float* __restrict__ Wr,
    const float* __restrict__ br)
{
    const int warp = (blockIdx.x * blockDim.x + threadIdx.x) >> 5;
    const int lane = threadIdx.x & 31;
    if (warp >= NTOK) return;
    const float* zr = z + (size_t)warp * CDIM;
    float p[NEXP];
#pragma unroll
    for (int e = 0; e < NEXP; e++) p[e] = 0.f;
    for (int c = lane; c < CDIM; c += 32) {
        float zv = zr[c];
        const float* wrow = Wr + c * NEXP;
#pragma unroll
        for (int e = 0; e < NEXP; e++) p[e] += zv * wrow[e];
    }
#pragma unroll
    for (int off = 16; off; off >>= 1)
#pragma unroll
        for (int e = 0; e < NEXP; e++) p[e] += __shfl_xor_sync(0xffffffffu, p[e], off);
    if (lane == 0) {
        float lg[NEXP];
#pragma unroll
        for (int e = 0; e < NEXP; e++) lg[e] = p[e] + br[e];
        int e0 = 0;
#pragma unroll
        for (int e = 1; e < NEXP; e++) if (lg[e] > lg[e0]) e0 = e;
        int e1 = (e0 == 0) ? 1 : 0;
#pragma unroll
        for (int e = 0; e < NEXP; e++) if (e != e0 && lg[e] > lg[e1]) e1 = e;
        float w0 = 1.f / (1.f + __expf(lg[e1] - lg[e0]));
        g_wgt[warp * 2] = w0;
        g_wgt[warp * 2 + 1] = 1.f - w0;
        g_eidx[warp * 2] = e0;
        g_eidx[warp * 2 + 1] = e1;
        atomicAdd(&g_cnt[e0], 1);
        atomicAdd(&g_cnt[e1], 1);
    }
}

__global__ void zero_kernel() {
    int t = threadIdx.x;
    if (t < NEXP) { g_cnt[t] = 0; g_cur[t] = 0; }
}

__global__ void prefix_kernel() {
    int s = 0;
    for (int e = 0; e < NEXP; e++) { g_off[e] = s; s += g_cnt[e]; }
}

__global__ __launch_bounds__(256) void assign_kernel() {
    int n = blockIdx.x * blockDim.x + threadIdx.x;
    if (n >= NTOK) return;
#pragma unroll
    for (int k = 0; k < 2; k++) {
        int e = g_eidx[n * 2 + k];
        int pos = atomicAdd(&g_cur[e], 1);
        int slot = g_off[e] + pos;
        g_slot[n * 2 + k] = slot;
        g_tok[slot] = n;
    }
}

// ---------------- final: out = x1 + sum_k w_k * (ye_k + b2[e_k]) -------------------
__global__ __launch_bounds__(256) void final_kernel(
    const float* __restrict__ b2, float* __restrict__ out)
{
    int i = blockIdx.x * blockDim.x + threadIdx.x;
    const int total = NTOK * CDIM / 4;
    if (i >= total) return;
    int n = i / (CDIM / 4);
    int c = (i % (CDIM / 4)) * 4;
    float w0 = g_wgt[n * 2], w1 = g_wgt[n * 2 + 1];
    int e0 = g_eidx[n * 2], e1 = g_eidx[n * 2 + 1];
    int s0 = g_slot[n * 2], s1 = g_slot[n * 2 + 1];
    float4 xv  = *(const float4*)&g_x1[(size_t)n * CDIM + c];
    float4 y0  = *(const float4*)&g_ye[(size_t)s0 * CDIM + c];
    float4 y1  = *(const float4*)&g_ye[(size_t)s1 * CDIM + c];
    float4 b0  = *(const float4*)&b2[(size_t)e0 * CDIM + c];
    float4 b1v = *(const float4*)&b2[(size_t)e1 * CDIM + c];
    float4 r;
    r.x = xv.x + w0 * (y0.x + b0.x) + w1 * (y1.x + b1v.x);
    r.y = xv.y + w0 * (y0.y + b0.y) + w1 * (y1.y + b1v.y);
    r.z = xv.z + w0 * (y0.z + b0.z) + w1 * (y1.z + b1v.z);
    r.w = xv.w + w0 * (y0.w + b0.w) + w1 * (y1.w + b1v.w);
    *(float4*)&out[(size_t)n * CDIM + c] = r;
}

// ---------------- launch -----------------------------------------------------------
extern "C" void kernel_launch(void* const* d_in, const int* in_sizes, int n_in,
                              void* d_out, int out_size)
{
    const float* x      = (const float*)d_in[0];
    const float* ln1_g  = (const float*)d_in[1];
    const float* ln1_b  = (const float*)d_in[2];
    const float* Wqkv   = (const float*)d_in[3];
    const float* bqkv   = (const float*)d_in[4];
    const float* Wproj  = (const float*)d_in[5];
    const float* bproj  = (const float*)d_in[6];
    const float* ln2_g  = (const float*)d_in[7];
    const float* ln2_b  = (const float*)d_in[8];
    const float* Wr     = (const float*)d_in[9];
    const float* br     = (const float*)d_in[10];
    const float* W1     = (const float*)d_in[11];
    const float* b1     = (const float*)d_in[12];
    const float* W2     = (const float*)d_in[13];
    const float* b2     = (const float*)d_in[14];
    float* out = (float*)d_out;

    static bool inited = false;
    static float *p_h, *p_qkv, *p_y, *p_x1, *p_z, *p_hid, *p_ye;
    if (!inited) {
        cudaGetSymbolAddress((void**)&p_h,   g_h);
        cudaGetSymbolAddress((void**)&p_qkv, g_qkv);
        cudaGetSymbolAddress((void**)&p_y,   g_y);
        cudaGetSymbolAddress((void**)&p_x1,  g_x1);
        cudaGetSymbolAddress((void**)&p_z,   g_z);
        cudaGetSymbolAddress((void**)&p_hid, g_hid);
        cudaGetSymbolAddress((void**)&p_ye,  g_ye);
        cudaFuncSetAttribute(attn_mma,
                             cudaFuncAttributeMaxDynamicSharedMemorySize, ATTN_SMEM2);
        cudaFuncSetAttribute(gemm_3xf16<true, false, false, 0>,
                             cudaFuncAttributeMaxDynamicSharedMemorySize, GEMM_SMEM);
        cudaFuncSetAttribute(gemm_3xf16<true, false, true, 0>,
                             cudaFuncAttributeMaxDynamicSharedMemorySize, GEMM_SMEM);
        cudaFuncSetAttribute(gemm_3xf16<true, true, false, 1>,
                             cudaFuncAttributeMaxDynamicSharedMemorySize, GEMM_SMEM);
        cudaFuncSetAttribute(gemm_3xf16<false, false, false, 2>,
                             cudaFuncAttributeMaxDynamicSharedMemorySize, GEMM_SMEM);
        inited = true;
    }

    // 1. LN1
    ln_kernel<<<NTOK, 256>>>(x, ln1_g, ln1_b, p_h);
    // 2. QKV GEMM (3xFP16 tensor cores)
    gemm_3xf16<true, false, false, 0><<<dim3(C3 / 128, NTOK / 128), 256, GEMM_SMEM>>>(
        p_h, Wqkv, bqkv, nullptr, p_qkv, C3, CDIM);
    // 3. flash attention (3xFP16 tensor cores)
    attn_mma<<<dim3(TSEQ / 128, NH, 4), 256, ATTN_SMEM2>>>(p_qkv, p_y);
    // 4. proj + residual
    gemm_3xf16<true, false, true, 0><<<dim3(CDIM / 128, NTOK / 128), 256, GEMM_SMEM>>>(
        p_y, Wproj, bproj, x, p_x1, CDIM, CDIM);
    // 5. LN2
    ln_kernel<<<NTOK, 256>>>(p_x1, ln2_g, ln2_b, p_z);
    // 6. routing
    zero_kernel<<<1, 32>>>();
    router_kernel<<<NTOK / 8, 256>>>(p_z, Wr, br);
    prefix_kernel<<<1, 1>>>();
    assign_kernel<<<NTOK / 256, 256>>>();
    // 7. MoE grouped GEMMs (sparse top-2, 3xFP16 tensor cores)
    gemm_3xf16<true, true, false, 1><<<dim3(DFF / 128, NTOK / 128, NEXP), 256, GEMM_SMEM>>>(
        p_z, W1, b1, nullptr, p_hid, DFF, CDIM);
    gemm_3xf16<false, false, false, 2><<<dim3(CDIM / 128, NTOK / 128, NEXP), 256, GEMM_SMEM>>>(
        p_hid, W2, nullptr, nullptr, p_ye, CDIM, DFF);
    // 8. weighted gather + residual
    final_kernel<<<(NTOK * CDIM / 4 + 255) / 256, 256>>>(b2, out);
}

// round 15
// speedup vs baseline: 3.8324x; 1.1120x over previous
#include <cuda_runtime.h>
#include <cuda_fp16.h>
#include <cstdint>

#define NTOK  8192
#define CDIM  768
#define C3    2304
#define DFF   3072
#define NSLOT 16384
#define NEXP  8
#define TSEQ  2048
#define NH    12
#define HD    64

// ---------------- scratch (static device globals; no allocations) ----------------
__device__ float  g_qkv[(size_t)NTOK * C3];
__device__ float  g_x1 [NTOK * CDIM];
__device__ float  g_ye [(size_t)NSLOT * CDIM];
__device__ __half g_hH [NTOK * CDIM],  g_hL [NTOK * CDIM];
__device__ __half g_yH [NTOK * CDIM],  g_yL [NTOK * CDIM];
__device__ __half g_zH [NTOK * CDIM],  g_zL [NTOK * CDIM];
__device__ __half g_hidH[(size_t)NSLOT * DFF], g_hidL[(size_t)NSLOT * DFF];
__device__ __half g_WqkvH[CDIM * C3],  g_WqkvL[CDIM * C3];
__device__ __half g_WprojH[CDIM * CDIM], g_WprojL[CDIM * CDIM];
__device__ __half g_W1H[(size_t)NEXP * CDIM * DFF], g_W1L[(size_t)NEXP * CDIM * DFF];
__device__ __half g_W2H[(size_t)NEXP * DFF * CDIM], g_W2L[(size_t)NEXP * DFF * CDIM];
__device__ float g_wgt[NTOK * 2];
__device__ int   g_eidx[NTOK * 2];
__device__ int   g_slot[NTOK * 2];
__device__ int   g_tok[NSLOT];
__device__ int   g_cnt[NEXP];
__device__ int   g_off[NEXP];
__device__ int   g_cur[NEXP];

// ---------------- fp16 helpers -----------------------------------------------------
__device__ __forceinline__ uint32_t packh(__half a, __half b) {
    return (uint32_t)__half_as_ushort(a) | ((uint32_t)__half_as_ushort(b) << 16);
}

__device__ __forceinline__ void split4(float4 v, uint2& h, uint2& l) {
    __half h0 = __float2half_rn(v.x), h1 = __float2half_rn(v.y);
    __half h2 = __float2half_rn(v.z), h3 = __float2half_rn(v.w);
    __half l0 = __float2half_rn(v.x - __half2float(h0));
    __half l1 = __float2half_rn(v.y - __half2float(h1));
    __half l2 = __float2half_rn(v.z - __half2float(h2));
    __half l3 = __float2half_rn(v.w - __half2float(h3));
    h.x = packh(h0, h1); h.y = packh(h2, h3);
    l.x = packh(l0, l1); l.y = packh(l2, l3);
}

__device__ __forceinline__ void mma_f16(float* c, const uint32_t* a, const uint32_t* b) {
    asm volatile(
        "mma.sync.aligned.m16n8k16.row.col.f32.f16.f16.f32 "
        "{%0,%1,%2,%3}, {%4,%5,%6,%7}, {%8,%9}, {%0,%1,%2,%3};\n"
        : "+f"(c[0]), "+f"(c[1]), "+f"(c[2]), "+f"(c[3])
        : "r"(a[0]), "r"(a[1]), "r"(a[2]), "r"(a[3]),
          "r"(b[0]), "r"(b[1]));
}

__device__ __forceinline__ void ldx4(uint32_t* r, uint32_t addr) {
    asm volatile("ldmatrix.sync.aligned.m8n8.x4.shared.b16 {%0,%1,%2,%3}, [%4];\n"
                 : "=r"(r[0]), "=r"(r[1]), "=r"(r[2]), "=r"(r[3]) : "r"(addr));
}
__device__ __forceinline__ void ldx2(uint32_t* r, uint32_t addr) {
    asm volatile("ldmatrix.sync.aligned.m8n8.x2.shared.b16 {%0,%1}, [%2];\n"
                 : "=r"(r[0]), "=r"(r[1]) : "r"(addr));
}
__device__ __forceinline__ void ldx2t(uint32_t* r, uint32_t addr) {
    asm volatile("ldmatrix.sync.aligned.m8n8.x2.trans.shared.b16 {%0,%1}, [%2];\n"
                 : "=r"(r[0]), "=r"(r[1]) : "r"(addr));
}
__device__ __forceinline__ void cp16h(__half* smemPtr, const __half* g, bool valid) {
    uint32_t s = (uint32_t)__cvta_generic_to_shared(smemPtr);
    int sz = valid ? 16 : 0;
    asm volatile("cp.async.ca.shared.global [%0], [%1], 16, %2;\n"
                 :: "r"(s), "l"(g), "r"(sz));
}
__device__ __forceinline__ void cp_commit() {
    asm volatile("cp.async.commit_group;\n");
}
template<int N> __device__ __forceinline__ void cp_wait() {
    asm volatile("cp.async.wait_group %0;\n" :: "n"(N));
}

// ---------------- weight pre-split --------------------------------------------------
__global__ __launch_bounds__(256) void splitw_kernel(
    const float* __restrict__ src, __half* __restrict__ dH,
    __half* __restrict__ dL, int n4)
{
    int i = blockIdx.x * blockDim.x + threadIdx.x;
    if (i >= n4) return;
    float4 v = ((const float4*)src)[i];
    uint2 h, l;
    split4(v, h, l);
    ((uint2*)dH)[i] = h;
    ((uint2*)dL)[i] = l;
}

// ---------------- LayerNorm -> hi/lo halves ----------------------------------------
__global__ __launch_bounds__(256) void ln_half(
    const float* __restrict__ x, const float* __restrict__ gam,
    const float* __restrict__ bet, __half* __restrict__ oH,
    __half* __restrict__ oL)
{
    const int row = blockIdx.x;
    const float* xr = x + (size_t)row * CDIM;
    float vals[3];
    float s1 = 0.f, s2 = 0.f;
#pragma unroll
    for (int u = 0; u < 3; u++) {
        float v = xr[threadIdx.x + u * 256];
        vals[u] = v; s1 += v; s2 += v * v;
    }
#pragma unroll
    for (int off = 16; off; off >>= 1) {
        s1 += __shfl_xor_sync(0xffffffffu, s1, off);
        s2 += __shfl_xor_sync(0xffffffffu, s2, off);
    }
    __shared__ float red1[8], red2[8];
    __shared__ float m_sh, r_sh;
    const int wid = threadIdx.x >> 5, lane = threadIdx.x & 31;
    if (lane == 0) { red1[wid] = s1; red2[wid] = s2; }
    __syncthreads();
    if (threadIdx.x == 0) {
        float a = 0.f, b = 0.f;
#pragma unroll
        for (int w = 0; w < 8; w++) { a += red1[w]; b += red2[w]; }
        float mean = a / CDIM;
        float var  = b / CDIM - mean * mean;
        m_sh = mean; r_sh = rsqrtf(var + 1e-5f);
    }
    __syncthreads();
    const float mean = m_sh, rstd = r_sh;
#pragma unroll
    for (int u = 0; u < 3; u++) {
        int c = threadIdx.x + u * 256;
        float v = (vals[u] - mean) * rstd * gam[c] + bet[c];
        __half h = __float2half_rn(v);
        oH[(size_t)row * CDIM + c] = h;
        oL[(size_t)row * CDIM + c] = __float2half_rn(v - __half2float(h));
    }
}

// ---------------- 3xFP16 GEMM on pre-split halves (cp.async producer) --------------
// 128x128x32 CTA tile, 8 warps, m16n8k16; D = AhBh + AhBl + AlBh.
// MODE 0: plain rows. MODE 1: gather rows via g_tok. MODE 2: direct expert rows.
// OUTH: epilogue emits hi/lo halves (for hid) instead of fp32.
#define LDAH 40
#define LDBH 136
#define A_HALFS (128 * LDAH)
#define B_HALFS (32 * LDBH)
#define STAGE_H (2 * A_HALFS + 2 * B_HALFS)
#define GEMM_SMEM (2 * STAGE_H * 2)

template<bool BIAS, bool RELU, bool RESID, int MODE, bool OUTH>
__global__ __launch_bounds__(256, 2) void gemm_f16pre(
    const __half* __restrict__ AH, const __half* __restrict__ AL,
    const __half* __restrict__ BH, const __half* __restrict__ BL,
    const float* __restrict__ bias, const float* __restrict__ resid,
    float* __restrict__ Cf, __half* __restrict__ CoH, __half* __restrict__ CoL,
    int N, int K)
{
    extern __shared__ __half smem[];

    int cnt = 0, base = 0;
    if (MODE) {
        const int e = blockIdx.z;
        cnt = g_cnt[e]; base = g_off[e];
        if ((int)blockIdx.y * 128 >= cnt) return;
        BH += (size_t)e * K * N;
        BL += (size_t)e * K * N;
        if (BIAS) bias += (size_t)e * N;
    }
    const int tid = threadIdx.x;
    const int rowBase = blockIdx.y * 128;
    const int colBase = blockIdx.x * 128;

    // A loader: thread covers rows rA and rA+64, 16B chunk ch
    const int rA = tid >> 2;
    const int ch = (tid & 3) * 8;
    const int r0i = rowBase + rA, r1i = rowBase + rA + 64;
    bool av0 = true, av1 = true;
    size_t aOff0, aOff1;
    if (MODE == 1) {
        av0 = r0i < cnt; av1 = r1i < cnt;
        aOff0 = (size_t)(av0 ? g_tok[base + r0i] : 0) * K;
        aOff1 = (size_t)(av1 ? g_tok[base + r1i] : 0) * K;
    } else if (MODE == 2) {
        av0 = r0i < cnt; av1 = r1i < cnt;
        aOff0 = (size_t)(base + (av0 ? r0i : 0)) * K;
        aOff1 = (size_t)(base + (av1 ? r1i : 0)) * K;
    } else {
        aOff0 = (size_t)r0i * K;
        aOff1 = (size_t)r1i * K;
    }
    // B loader: thread covers k-rows kr and kr+16, 16B chunk bch
    const int kr = tid >> 4;
    const int bch = (tid & 15) * 8;

    const int lane = tid & 31, wid = tid >> 5;
    const int g  = lane >> 2;
    const int t4 = lane & 3;
    const int lane15 = lane & 15;
    const int warpM = (wid >> 2) * 64;
    const int warpN = (wid & 3) * 32;

    float c[4][4][4];
#pragma unroll
    for (int i = 0; i < 4; i++)
#pragma unroll
        for (int j = 0; j < 4; j++)
#pragma unroll
            for (int q = 0; q < 4; q++) c[i][j][q] = 0.f;

    auto load_stage = [&](int k0, __half* st) {
        __half* AsH = st;
        __half* AsL = st + A_HALFS;
        __half* BsH = st + 2 * A_HALFS;
        __half* BsL = BsH + B_HALFS;
        cp16h(&AsH[rA * LDAH + ch],        AH + aOff0 + k0 + ch, av0);
        cp16h(&AsH[(rA + 64) * LDAH + ch], AH + aOff1 + k0 + ch, av1);
        cp16h(&AsL[rA * LDAH + ch],        AL + aOff0 + k0 + ch, av0);
        cp16h(&AsL[(rA + 64) * LDAH + ch], AL + aOff1 + k0 + ch, av1);
        cp16h(&BsH[kr * LDBH + bch],        BH + (size_t)(k0 + kr) * N + colBase + bch, true);
        cp16h(&BsH[(kr + 16) * LDBH + bch], BH + (size_t)(k0 + kr + 16) * N + colBase + bch, true);
        cp16h(&BsL[kr * LDBH + bch],        BL + (size_t)(k0 + kr) * N + colBase + bch, true);
        cp16h(&BsL[(kr + 16) * LDBH + bch], BL + (size_t)(k0 + kr + 16) * N + colBase + bch, true);
    };

    const uint32_t smemAddr = (uint32_t)__cvta_generic_to_shared(smem);
    const int nIters = K / 32;
    load_stage(0, smem);
    cp_commit();

    for (int it = 0; it < nIters; it++) {
        const uint32_t st = smemAddr + (uint32_t)((it & 1) * STAGE_H * 2);
        if (it + 1 < nIters) {
            load_stage((it + 1) * 32, smem + (size_t)((it + 1) & 1) * STAGE_H);
            cp_commit();
            cp_wait<1>();
        } else {
            cp_wait<0>();
        }
        __syncthreads();

        const uint32_t aH = st + (uint32_t)(((warpM + lane15) * LDAH + (lane >> 4) * 8) * 2);
        const uint32_t aL = aH + A_HALFS * 2;
        const uint32_t bH = st + (uint32_t)(2 * A_HALFS * 2) +
                            (uint32_t)((lane15 * LDBH + warpN) * 2);
        const uint32_t bL = bH + B_HALFS * 2;

#pragma unroll
        for (int ks = 0; ks < 2; ks++) {
            const uint32_t aks = ks * 32;
            const uint32_t bks = ks * 16 * LDBH * 2;
            uint32_t bh[4][2], bl[4][2];
#pragma unroll
            for (int nt = 0; nt < 4; nt++) {
                ldx2t(bh[nt], bH + bks + nt * 16);
                ldx2t(bl[nt], bL + bks + nt * 16);
            }
#pragma unroll
            for (int mt = 0; mt < 4; mt++) {
                uint32_t ah[4], al[4];
                ldx4(ah, aH + aks + mt * 16 * LDAH * 2);
                ldx4(al, aL + aks + mt * 16 * LDAH * 2);
#pragma unroll
                for (int nt = 0; nt < 4; nt++) {
                    mma_f16(c[mt][nt], ah, bl[nt]);
                    mma_f16(c[mt][nt], al, bh[nt]);
                    mma_f16(c[mt][nt], ah, bh[nt]);
                }
            }
        }
        __syncthreads();
    }

    // epilogue
#pragma unroll
    for (int mt = 0; mt < 4; mt++) {
        const int r0 = rowBase + warpM + mt * 16 + g;
#pragma unroll
        for (int hh = 0; hh < 2; hh++) {
            const int r = r0 + hh * 8;
            if (MODE && r >= cnt) continue;
            const size_t orow = MODE ? (size_t)(base + r) : (size_t)r;
            const float* rp = RESID ? resid + (size_t)r * N : nullptr;
#pragma unroll
            for (int nt = 0; nt < 4; nt++) {
                const int col = colBase + warpN + nt * 8 + 2 * t4;
                float v0 = c[mt][nt][hh * 2 + 0];
                float v1 = c[mt][nt][hh * 2 + 1];
                if (BIAS) { v0 += bias[col]; v1 += bias[col + 1]; }
                if (RESID) { v0 += rp[col]; v1 += rp[col + 1]; }
                if (RELU) { v0 = fmaxf(v0, 0.f); v1 = fmaxf(v1, 0.f); }
                if (OUTH) {
                    __half h0 = __float2half_rn(v0), h1 = __float2half_rn(v1);
                    *(__half2*)(CoH + orow * N + col) = __halves2half2(h0, h1);
                    *(__half2*)(CoL + orow * N + col) = __halves2half2(
                        __float2half_rn(v0 - __half2float(h0)),
                        __float2half_rn(v1 - __half2float(h1)));
                } else {
                    float2 vv; vv.x = v0; vv.y = v1;
                    *(float2*)(Cf + orow * N + col) = vv;
                }
            }
        }
    }
}

// ---------------- 3xFP16 flash attention (epilogue writes hi/lo y) -----------------
#define ASTR 72
#define ATTN_KH 0
#define ATTN_KL (64 * ASTR)
#define ATTN_VH (2 * 64 * ASTR)
#define ATTN_VL (3 * 64 * ASTR)
#define ATTN_SMEM2 (4 * 64 * ASTR * 2)

__global__ __launch_bounds__(256) void attn_mma(
    const float* __restrict__ qkv)
{
    extern __shared__ __half sm[];
    const int qt = blockIdx.x;
    const int hd = blockIdx.y;
    const int b  = blockIdx.z;
    const int tid  = threadIdx.x;
    const int lane = tid & 31;
    const int w    = tid >> 5;
    const int g    = lane >> 2;
    const int t4   = lane & 3;
    const int lane15 = lane & 15;
    const int qRow0 = qt * 128;
    const float* qbase = qkv + (size_t)b * TSEQ * C3 + hd * HD;
    const uint32_t smb = (uint32_t)__cvta_generic_to_shared(sm);

    #pragma unroll
    for (int u = 0; u < 8; u++) {
        int lin = tid + u * 256;
        int r = lin >> 4, c4 = (lin & 15) * 4;
        float4 v = *(const float4*)(qbase + (size_t)(qRow0 + r) * C3 + c4);
        uint2 hh, ll;
        split4(v, hh, ll);
        *(uint2*)&sm[r * ASTR + c4] = hh;
        *(uint2*)&sm[128 * ASTR + r * ASTR + c4] = ll;
    }
    __syncthreads();

    uint32_t qh[4][4], ql[4][4];
    {
        int row = (lane15 < 8) ? (8 * w + lane15) : (64 + 8 * w + lane15 - 8);
        uint32_t base = smb + (uint32_t)((row * ASTR + (lane >> 4) * 8) * 2);
        #pragma unroll
        for (int ks = 0; ks < 4; ks++) {
            ldx4(qh[ks], base + ks * 32);
            ldx4(ql[ks], base + ks * 32 + 128 * ASTR * 2);
        }
    }
    __syncthreads();

    float o[8][4];
    #pragma unroll
    for (int i = 0; i < 8; i++)
        #pragma unroll
        for (int j = 0; j < 4; j++) o[i][j] = 0.f;
    float m0 = -1e30f, m1 = -1e30f, l0 = 0.f, l1 = 0.f;
    const int row0 = qRow0 + 8 * w + g;
    const int row1 = row0 + 64;
    const int row1max = qRow0 + 64 + 8 * w + 7;
    const float scale = 0.125f;
    const int nTiles = qt * 2 + 2;

    for (int t = 0; t < nTiles; t++) {
        const int j0 = t * 64;
        #pragma unroll
        for (int u = 0; u < 4; u++) {
            int lin = tid + u * 256;
            int r = lin >> 4, c4 = (lin & 15) * 4;
            float4 kv = *(const float4*)(qbase + CDIM + (size_t)(j0 + r) * C3 + c4);
            uint2 hh, ll;
            split4(kv, hh, ll);
            *(uint2*)&sm[ATTN_KH + r * ASTR + c4] = hh;
            *(uint2*)&sm[ATTN_KL + r * ASTR + c4] = ll;
            float4 vv = *(const float4*)(qbase + 2 * CDIM + (size_t)(j0 + r) * C3 + c4);
            split4(vv, hh, ll);
            *(uint2*)&sm[ATTN_VH + r * ASTR + c4] = hh;
            *(uint2*)&sm[ATTN_VL + r * ASTR + c4] = ll;
        }
        __syncthreads();

        if (j0 <= row1max) {
            float s[8][4];
            #pragma unroll
            for (int i = 0; i < 8; i++)
                #pragma unroll
                for (int j = 0; j < 4; j++) s[i][j] = 0.f;
            {
                const uint32_t kb = smb + (uint32_t)((((lane15 & 7) * ASTR) + (lane15 >> 3) * 8) * 2);
                #pragma unroll
                for (int nt = 0; nt < 8; nt++) {
                    const uint32_t knt = kb + (uint32_t)(nt * 8 * ASTR * 2);
                    #pragma unroll
                    for (int ks = 0; ks < 4; ks++) {
                        uint32_t kh2[2], kl2[2];
                        ldx2(kh2, knt + ks * 32 + ATTN_KH * 2);
                        ldx2(kl2, knt + ks * 32 + ATTN_KL * 2);
                        mma_f16(s[nt], qh[ks], kl2);
                        mma_f16(s[nt], ql[ks], kh2);
                        mma_f16(s[nt], qh[ks], kh2);
                    }
                }
            }
            float mloc0 = -1e30f, mloc1 = -1e30f;
            #pragma unroll
            for (int nt = 0; nt < 8; nt++) {
                int kg = j0 + nt * 8 + 2 * t4;
                s[nt][0] = (kg     <= row0) ? s[nt][0] * scale : -1e30f;
                s[nt][1] = (kg + 1 <= row0) ? s[nt][1] * scale : -1e30f;
                s[nt][2] = (kg     <= row1) ? s[nt][2] * scale : -1e30f;
                s[nt][3] = (kg + 1 <= row1) ? s[nt][3] * scale : -1e30f;
                mloc0 = fmaxf(mloc0, fmaxf(s[nt][0], s[nt][1]));
                mloc1 = fmaxf(mloc1, fmaxf(s[nt][2], s[nt][3]));
            }
            mloc0 = fmaxf(mloc0, __shfl_xor_sync(0xffffffffu, mloc0, 1));
            mloc0 = fmaxf(mloc0, __shfl_xor_sync(0xffffffffu, mloc0, 2));
            mloc1 = fmaxf(mloc1, __shfl_xor_sync(0xffffffffu, mloc1, 1));
            mloc1 = fmaxf(mloc1, __shfl_xor_sync(0xffffffffu, mloc1, 2));
            float mn0 = fmaxf(m0, mloc0), mn1 = fmaxf(m1, mloc1);
            float a0 = __expf(m0 - mn0), a1 = __expf(m1 - mn1);
            float ls0 = 0.f, ls1 = 0.f;
            #pragma unroll
            for (int nt = 0; nt < 8; nt++) {
                s[nt][0] = __expf(s[nt][0] - mn0);
                s[nt][1] = __expf(s[nt][1] - mn0);
                s[nt][2] = __expf(s[nt][2] - mn1);
                s[nt][3] = __expf(s[nt][3] - mn1);
                ls0 += s[nt][0] + s[nt][1];
                ls1 += s[nt][2] + s[nt][3];
            }
            ls0 += __shfl_xor_sync(0xffffffffu, ls0, 1);
            ls0 += __shfl_xor_sync(0xffffffffu, ls0, 2);
            ls1 += __shfl_xor_sync(0xffffffffu, ls1, 1);
            ls1 += __shfl_xor_sync(0xffffffffu, ls1, 2);
            l0 = l0 * a0 + ls0;  l1 = l1 * a1 + ls1;
            m0 = mn0;  m1 = mn1;
            #pragma unroll
            for (int dt = 0; dt < 8; dt++) {
                o[dt][0] *= a0; o[dt][1] *= a0;
                o[dt][2] *= a1; o[dt][3] *= a1;
            }
            const uint32_t vb = smb + (uint32_t)((lane15 * ASTR) * 2);
            #pragma unroll
            for (int ks = 0; ks < 4; ks++) {
                uint32_t ph[4], pl[4];
                #pragma unroll
                for (int half16 = 0; half16 < 2; half16++) {
                    int nt = ks * 2 + half16;
                    __half h0 = __float2half_rn(s[nt][0]);
                    __half h1 = __float2half_rn(s[nt][1]);
                    __half h2 = __float2half_rn(s[nt][2]);
                    __half h3 = __float2half_rn(s[nt][3]);
                    ph[half16 * 2 + 0] = packh(h0, h1);
                    ph[half16 * 2 + 1] = packh(h2, h3);
                    pl[half16 * 2 + 0] = packh(
                        __float2half_rn(s[nt][0] - __half2float(h0)),
                        __float2half_rn(s[nt][1] - __half2float(h1)));
                    pl[half16 * 2 + 1] = packh(
                        __float2half_rn(s[nt][2] - __half2float(h2)),
                        __float2half_rn(s[nt][3] - __half2float(h3)));
                }
                uint32_t pha[4] = { ph[0], ph[1], ph[2], ph[3] };
                uint32_t pla[4] = { pl[0], pl[1], pl[2], pl[3] };
                const uint32_t vks = vb + (uint32_t)(ks * 16 * ASTR * 2);
                #pragma unroll
                for (int dt = 0; dt < 8; dt++) {
                    uint32_t vh2[2], vl2[2];
                    ldx2t(vh2, vks + dt * 16 + ATTN_VH * 2);
                    ldx2t(vl2, vks + dt * 16 + ATTN_VL * 2);
                    mma_f16(o[dt], pha, vl2);
                    mma_f16(o[dt], pla, vh2);
                    mma_f16(o[dt], pha, vh2);
                }
            }
        }
        __syncthreads();
    }

    // epilogue: write y as hi/lo halves for the proj GEMM
    const float inv0 = 1.f / l0, inv1 = 1.f / l1;
    const size_t y0off = (size_t)(b * TSEQ + row0) * CDIM + hd * HD;
    const size_t y1off = (size_t)(b * TSEQ + row1) * CDIM + hd * HD;
    #pragma unroll
    for (int dt = 0; dt < 8; dt++) {
        int col = dt * 8 + 2 * t4;
        float v00 = o[dt][0] * inv0, v01 = o[dt][1] * inv0;
        float v10 = o[dt][2] * inv1, v11 = o[dt][3] * inv1;
        __half h00 = __float2half_rn(v00), h01 = __float2half_rn(v01);
        __half h10 = __float2half_rn(v10), h11 = __float2half_rn(v11);
        *(__half2*)(g_yH + y0off + col) = __halves2half2(h00, h01);
        *(__half2*)(g_yL + y0off + col) = __halves2half2(
            __float2half_rn(v00 - __half2float(h00)),
            __float2half_rn(v01 - __half2float(h01)));
        *(__half2*)(g_yH + y1off + col) = __halves2half2(h10, h11);
        *(__half2*)(g_yL + y1off + col) = __halves2half2(
            __float2half_rn(v10 - __half2float(h10)),
            __float2half_rn(v11 - __half2float(h11)));
    }
}

// ---------------- router (reads hi+lo z) -------------------------------------------
__global__ __launch_bounds__(256) void router_kernel(
    const float* __restrict__ Wr, const float* __restrict__ br)
{
    const int warp = (blockIdx.x * blockDim.x + threadIdx.x) >> 5;
    const int lane = threadIdx.x & 31;
    if (warp >= NTOK) return;
    float p[NEXP];
#pragma unroll
    for (int e = 0; e < NEXP; e++) p[e] = 0.f;
    for (int c = lane; c < CDIM; c += 32) {
        float zv = __half2float(g_zH[(size_t)warp * CDIM + c]) +
                   __half2float(g_zL[(size_t)warp * CDIM + c]);
        const float* wrow = Wr + c * NEXP;
#pragma unroll
        for (int e = 0; e < NEXP; e++) p[e] += zv * wrow[e];
    }
#pragma unroll
    for (int off = 16; off; off >>= 1)
#pragma unroll
        for (int e = 0; e < NEXP; e++) p[e] += __shfl_xor_sync(0xffffffffu, p[e], off);
    if (lane == 0) {
        float lg[NEXP];
#pragma unroll
        for (int e = 0; e < NEXP; e++) lg[e] = p[e] + br[e];
        int e0 = 0;
#pragma unroll
        for (int e = 1; e < NEXP; e++) if (lg[e] > lg[e0]) e0 = e;
        int e1 = (e0 == 0) ? 1 : 0;
#pragma unroll
        for (int e = 0; e < NEXP; e++) if (e != e0 && lg[e] > lg[e1]) e1 = e;
        float w0 = 1.f / (1.f + __expf(lg[e1] - lg[e0]));
        g_wgt[warp * 2] = w0;
        g_wgt[warp * 2 + 1] = 1.f - w0;
        g_eidx[warp * 2] = e0;
        g_eidx[warp * 2 + 1] = e1;
        atomicAdd(&g_cnt[e0], 1);
        atomicAdd(&g_cnt[e1], 1);
    }
}

__global__ void zero_kernel() {
    int t = threadIdx.x;
    if (t < NEXP) { g_cnt[t] = 0; g_cur[t] = 0; }
}

__global__ void prefix_kernel() {
    int s = 0;
    for (int e = 0; e < NEXP; e++) { g_off[e] = s; s += g_cnt[e]; }
}

__global__ __launch_bounds__(256) void assign_kernel() {
    int n = blockIdx.x * blockDim.x + threadIdx.x;
    if (n >= NTOK) return;
#pragma unroll
    for (int k = 0; k < 2; k++) {
        int e = g_eidx[n * 2 + k];
        int pos = atomicAdd(&g_cur[e], 1);
        int slot = g_off[e] + pos;
        g_slot[n * 2 + k] = slot;
        g_tok[slot] = n;
    }
}

// ---------------- final: out = x1 + sum_k w_k * (ye_k + b2[e_k]) -------------------
__global__ __launch_bounds__(256) void final_kernel(
    const float* __restrict__ b2, float* __restrict__ out)
{
    int i = blockIdx.x * blockDim.x + threadIdx.x;
    const int total = NTOK * CDIM / 4;
    if (i >= total) return;
    int n = i / (CDIM / 4);
    int c = (i % (CDIM / 4)) * 4;
    float w0 = g_wgt[n * 2], w1 = g_wgt[n * 2 + 1];
    int e0 = g_eidx[n * 2], e1 = g_eidx[n * 2 + 1];
    int s0 = g_slot[n * 2], s1 = g_slot[n * 2 + 1];
    float4 xv  = *(const float4*)&g_x1[(size_t)n * CDIM + c];
    float4 y0  = *(const float4*)&g_ye[(size_t)s0 * CDIM + c];
    float4 y1  = *(const float4*)&g_ye[(size_t)s1 * CDIM + c];
    float4 b0  = *(const float4*)&b2[(size_t)e0 * CDIM + c];
    float4 b1v = *(const float4*)&b2[(size_t)e1 * CDIM + c];
    float4 r;
    r.x = xv.x + w0 * (y0.x + b0.x) + w1 * (y1.x + b1v.x);
    r.y = xv.y + w0 * (y0.y + b0.y) + w1 * (y1.y + b1v.y);
    r.z = xv.z + w0 * (y0.z + b0.z) + w1 * (y1.z + b1v.z);
    r.w = xv.w + w0 * (y0.w + b0.w) + w1 * (y1.w + b1v.w);
    *(float4*)&out[(size_t)n * CDIM + c] = r;
}

// ---------------- launch -----------------------------------------------------------
extern "C" void kernel_launch(void* const* d_in, const int* in_sizes, int n_in,
                              void* d_out, int out_size)
{
    const float* x      = (const float*)d_in[0];
    const float* ln1_g  = (const float*)d_in[1];
    const float* ln1_b  = (const float*)d_in[2];
    const float* Wqkv   = (const float*)d_in[3];
    const float* bqkv   = (const float*)d_in[4];
    const float* Wproj  = (const float*)d_in[5];
    const float* bproj  = (const float*)d_in[6];
    const float* ln2_g  = (const float*)d_in[7];
    const float* ln2_b  = (const float*)d_in[8];
    const float* Wr     = (const float*)d_in[9];
    const float* br     = (const float*)d_in[10];
    const float* W1     = (const float*)d_in[11];
    const float* b1     = (const float*)d_in[12];
    const float* W2     = (const float*)d_in[13];
    const float* b2     = (const float*)d_in[14];
    float* out = (float*)d_out;

    static bool inited = false;
    static float *p_qkv, *p_x1, *p_ye;
    static __half *p_hH, *p_hL, *p_yH, *p_yL, *p_zH, *p_zL, *p_hidH, *p_hidL;
    static __half *p_WqkvH, *p_WqkvL, *p_WprojH, *p_WprojL;
    static __half *p_W1H, *p_W1L, *p_W2H, *p_W2L;
    if (!inited) {
        cudaGetSymbolAddress((void**)&p_qkv, g_qkv);
        cudaGetSymbolAddress((void**)&p_x1,  g_x1);
        cudaGetSymbolAddress((void**)&p_ye,  g_ye);
        cudaGetSymbolAddress((void**)&p_hH,  g_hH);
        cudaGetSymbolAddress((void**)&p_hL,  g_hL);
        cudaGetSymbolAddress((void**)&p_yH,  g_yH);
        cudaGetSymbolAddress((void**)&p_yL,  g_yL);
        cudaGetSymbolAddress((void**)&p_zH,  g_zH);
        cudaGetSymbolAddress((void**)&p_zL,  g_zL);
        cudaGetSymbolAddress((void**)&p_hidH, g_hidH);
        cudaGetSymbolAddress((void**)&p_hidL, g_hidL);
        cudaGetSymbolAddress((void**)&p_WqkvH, g_WqkvH);
        cudaGetSymbolAddress((void**)&p_WqkvL, g_WqkvL);
        cudaGetSymbolAddress((void**)&p_WprojH, g_WprojH);
        cudaGetSymbolAddress((void**)&p_WprojL, g_WprojL);
        cudaGetSymbolAddress((void**)&p_W1H, g_W1H);
        cudaGetSymbolAddress((void**)&p_W1L, g_W1L);
        cudaGetSymbolAddress((void**)&p_W2H, g_W2H);
        cudaGetSymbolAddress((void**)&p_W2L, g_W2L);
        cudaFuncSetAttribute(attn_mma,
                             cudaFuncAttributeMaxDynamicSharedMemorySize, ATTN_SMEM2);
        cudaFuncSetAttribute(gemm_f16pre<true, false, false, 0, false>,
                             cudaFuncAttributeMaxDynamicSharedMemorySize, GEMM_SMEM);
        cudaFuncSetAttribute(gemm_f16pre<true, false, true, 0, false>,
                             cudaFuncAttributeMaxDynamicSharedMemorySize, GEMM_SMEM);
        cudaFuncSetAttribute(gemm_f16pre<true, true, false, 1, true>,
                             cudaFuncAttributeMaxDynamicSharedMemorySize, GEMM_SMEM);
        cudaFuncSetAttribute(gemm_f16pre<false, false, false, 2, false>,
                             cudaFuncAttributeMaxDynamicSharedMemorySize, GEMM_SMEM);
        inited = true;
    }

    // 0. pre-split weights into hi/lo halves
    splitw_kernel<<<(CDIM * C3 / 4 + 255) / 256, 256>>>(Wqkv, p_WqkvH, p_WqkvL, CDIM * C3 / 4);
    splitw_kernel<<<(CDIM * CDIM / 4 + 255) / 256, 256>>>(Wproj, p_WprojH, p_WprojL, CDIM * CDIM / 4);
    splitw_kernel<<<(NEXP * CDIM * DFF / 4 + 255) / 256, 256>>>(W1, p_W1H, p_W1L, NEXP * CDIM * DFF / 4);
    splitw_kernel<<<(NEXP * DFF * CDIM / 4 + 255) / 256, 256>>>(W2, p_W2H, p_W2L, NEXP * DFF * CDIM / 4);

    // 1. LN1 -> hi/lo halves
    ln_half<<<NTOK, 256>>>(x, ln1_g, ln1_b, p_hH, p_hL);
    // 2. QKV GEMM
    gemm_f16pre<true, false, false, 0, false><<<dim3(C3 / 128, NTOK / 128), 256, GEMM_SMEM>>>(
        p_hH, p_hL, p_WqkvH, p_WqkvL, bqkv, nullptr, p_qkv, nullptr, nullptr, C3, CDIM);
    // 3. flash attention (writes yH/yL)
    attn_mma<<<dim3(TSEQ / 128, NH, 4), 256, ATTN_SMEM2>>>(p_qkv);
    // 4. proj + residual
    gemm_f16pre<true, false, true, 0, false><<<dim3(CDIM / 128, NTOK / 128), 256, GEMM_SMEM>>>(
        p_yH, p_yL, p_WprojH, p_WprojL, bproj, x, p_x1, nullptr, nullptr, CDIM, CDIM);
    // 5. LN2 -> hi/lo halves
    ln_half<<<NTOK, 256>>>(p_x1, ln2_g, ln2_b, p_zH, p_zL);
    // 6. routing
    zero_kernel<<<1, 32>>>();
    router_kernel<<<NTOK / 8, 256>>>(Wr, br);
    prefix_kernel<<<1, 1>>>();
    assign_kernel<<<NTOK / 256, 256>>>();
    // 7. MoE grouped GEMMs
    gemm_f16pre<true, true, false, 1, true><<<dim3(DFF / 128, NTOK / 128, NEXP), 256, GEMM_SMEM>>>(
        p_zH, p_zL, p_W1H, p_W1L, b1, nullptr, nullptr, p_hidH, p_hidL, DFF, CDIM);
    gemm_f16pre<false, false, false, 2, false><<<dim3(CDIM / 128, NTOK / 128, NEXP), 256, GEMM_SMEM>>>(
        p_hidH, p_hidL, p_W2H, p_W2L, nullptr, nullptr, p_ye, nullptr, nullptr, CDIM, DFF);
    // 8. weighted gather + residual
    final_kernel<<<(NTOK * CDIM / 4 + 255) / 256, 256>>>(b2, out);
}

// round 16
// speedup vs baseline: 4.0409x; 1.0544x over previous
#include <cuda_runtime.h>
#include <cuda_fp16.h>
#include <cstdint>

#define NTOK  8192
#define CDIM  768
#define C3    2304
#define DFF   3072
#define NSLOT 16384
#define NEXP  8
#define TSEQ  2048
#define NH    12
#define HD    64

// ---------------- scratch (static device globals; no allocations) ----------------
__device__ float  g_x1 [NTOK * CDIM];
__device__ float  g_ye [(size_t)NSLOT * CDIM];
__device__ __half g_qkvH[(size_t)NTOK * C3], g_qkvL[(size_t)NTOK * C3];
__device__ __half g_hH [NTOK * CDIM],  g_hL [NTOK * CDIM];
__device__ __half g_yH [NTOK * CDIM],  g_yL [NTOK * CDIM];
__device__ __half g_zH [NTOK * CDIM],  g_zL [NTOK * CDIM];
__device__ __half g_hidH[(size_t)NSLOT * DFF], g_hidL[(size_t)NSLOT * DFF];
__device__ __half g_WqkvH[CDIM * C3],  g_WqkvL[CDIM * C3];
__device__ __half g_WprojH[CDIM * CDIM], g_WprojL[CDIM * CDIM];
__device__ __half g_W1H[(size_t)NEXP * CDIM * DFF], g_W1L[(size_t)NEXP * CDIM * DFF];
__device__ __half g_W2H[(size_t)NEXP * DFF * CDIM], g_W2L[(size_t)NEXP * DFF * CDIM];
__device__ float g_wgt[NTOK * 2];
__device__ int   g_eidx[NTOK * 2];
__device__ int   g_slot[NTOK * 2];
__device__ int   g_tok[NSLOT];
__device__ int   g_cnt[NEXP];
__device__ int   g_off[NEXP];
__device__ int   g_cur[NEXP];

// ---------------- fp16 helpers -----------------------------------------------------
__device__ __forceinline__ uint32_t packh(__half a, __half b) {
    return (uint32_t)__half_as_ushort(a) | ((uint32_t)__half_as_ushort(b) << 16);
}

__device__ __forceinline__ void split4(float4 v, uint2& h, uint2& l) {
    __half h0 = __float2half_rn(v.x), h1 = __float2half_rn(v.y);
    __half h2 = __float2half_rn(v.z), h3 = __float2half_rn(v.w);
    __half l0 = __float2half_rn(v.x - __half2float(h0));
    __half l1 = __float2half_rn(v.y - __half2float(h1));
    __half l2 = __float2half_rn(v.z - __half2float(h2));
    __half l3 = __float2half_rn(v.w - __half2float(h3));
    h.x = packh(h0, h1); h.y = packh(h2, h3);
    l.x = packh(l0, l1); l.y = packh(l2, l3);
}

__device__ __forceinline__ void mma_f16(float* c, const uint32_t* a, const uint32_t* b) {
    asm volatile(
        "mma.sync.aligned.m16n8k16.row.col.f32.f16.f16.f32 "
        "{%0,%1,%2,%3}, {%4,%5,%6,%7}, {%8,%9}, {%0,%1,%2,%3};\n"
        : "+f"(c[0]), "+f"(c[1]), "+f"(c[2]), "+f"(c[3])
        : "r"(a[0]), "r"(a[1]), "r"(a[2]), "r"(a[3]),
          "r"(b[0]), "r"(b[1]));
}

__device__ __forceinline__ void ldx4(uint32_t* r, uint32_t addr) {
    asm volatile("ldmatrix.sync.aligned.m8n8.x4.shared.b16 {%0,%1,%2,%3}, [%4];\n"
                 : "=r"(r[0]), "=r"(r[1]), "=r"(r[2]), "=r"(r[3]) : "r"(addr));
}
__device__ __forceinline__ void ldx2(uint32_t* r, uint32_t addr) {
    asm volatile("ldmatrix.sync.aligned.m8n8.x2.shared.b16 {%0,%1}, [%2];\n"
                 : "=r"(r[0]), "=r"(r[1]) : "r"(addr));
}
__device__ __forceinline__ void ldx2t(uint32_t* r, uint32_t addr) {
    asm volatile("ldmatrix.sync.aligned.m8n8.x2.trans.shared.b16 {%0,%1}, [%2];\n"
                 : "=r"(r[0]), "=r"(r[1]) : "r"(addr));
}
__device__ __forceinline__ void cp16h(__half* smemPtr, const __half* g, bool valid) {
    uint32_t s = (uint32_t)__cvta_generic_to_shared(smemPtr);
    int sz = valid ? 16 : 0;
    asm volatile("cp.async.ca.shared.global [%0], [%1], 16, %2;\n"
                 :: "r"(s), "l"(g), "r"(sz));
}
__device__ __forceinline__ void cp_commit() {
    asm volatile("cp.async.commit_group;\n");
}
template<int N> __device__ __forceinline__ void cp_wait() {
    asm volatile("cp.async.wait_group %0;\n" :: "n"(N));
}

// ---------------- weight pre-split --------------------------------------------------
__global__ __launch_bounds__(256) void splitw_kernel(
    const float* __restrict__ src, __half* __restrict__ dH,
    __half* __restrict__ dL, int n4)
{
    int i = blockIdx.x * blockDim.x + threadIdx.x;
    if (i >= n4) return;
    float4 v = ((const float4*)src)[i];
    uint2 h, l;
    split4(v, h, l);
    ((uint2*)dH)[i] = h;
    ((uint2*)dL)[i] = l;
}

// ---------------- LayerNorm -> hi/lo halves ----------------------------------------
__global__ __launch_bounds__(256) void ln_half(
    const float* __restrict__ x, const float* __restrict__ gam,
    const float* __restrict__ bet, __half* __restrict__ oH,
    __half* __restrict__ oL)
{
    const int row = blockIdx.x;
    const float* xr = x + (size_t)row * CDIM;
    float vals[3];
    float s1 = 0.f, s2 = 0.f;
#pragma unroll
    for (int u = 0; u < 3; u++) {
        float v = xr[threadIdx.x + u * 256];
        vals[u] = v; s1 += v; s2 += v * v;
    }
#pragma unroll
    for (int off = 16; off; off >>= 1) {
        s1 += __shfl_xor_sync(0xffffffffu, s1, off);
        s2 += __shfl_xor_sync(0xffffffffu, s2, off);
    }
    __shared__ float red1[8], red2[8];
    __shared__ float m_sh, r_sh;
    const int wid = threadIdx.x >> 5, lane = threadIdx.x & 31;
    if (lane == 0) { red1[wid] = s1; red2[wid] = s2; }
    __syncthreads();
    if (threadIdx.x == 0) {
        float a = 0.f, b = 0.f;
#pragma unroll
        for (int w = 0; w < 8; w++) { a += red1[w]; b += red2[w]; }
        float mean = a / CDIM;
        float var  = b / CDIM - mean * mean;
        m_sh = mean; r_sh = rsqrtf(var + 1e-5f);
    }
    __syncthreads();
    const float mean = m_sh, rstd = r_sh;
#pragma unroll
    for (int u = 0; u < 3; u++) {
        int c = threadIdx.x + u * 256;
        float v = (vals[u] - mean) * rstd * gam[c] + bet[c];
        __half h = __float2half_rn(v);
        oH[(size_t)row * CDIM + c] = h;
        oL[(size_t)row * CDIM + c] = __float2half_rn(v - __half2float(h));
    }
}

// ---------------- 3xFP16 GEMM on pre-split halves (cp.async producer) --------------
#define LDAH 40
#define LDBH 136
#define A_HALFS (128 * LDAH)
#define B_HALFS (32 * LDBH)
#define STAGE_H (2 * A_HALFS + 2 * B_HALFS)
#define GEMM_SMEM (2 * STAGE_H * 2)

template<bool BIAS, bool RELU, bool RESID, int MODE, bool OUTH>
__global__ __launch_bounds__(256, 2) void gemm_f16pre(
    const __half* __restrict__ AH, const __half* __restrict__ AL,
    const __half* __restrict__ BH, const __half* __restrict__ BL,
    const float* __restrict__ bias, const float* __restrict__ resid,
    float* __restrict__ Cf, __half* __restrict__ CoH, __half* __restrict__ CoL,
    int N, int K)
{
    extern __shared__ __half smem[];

    int cnt = 0, base = 0;
    if (MODE) {
        const int e = blockIdx.z;
        cnt = g_cnt[e]; base = g_off[e];
        if ((int)blockIdx.y * 128 >= cnt) return;
        BH += (size_t)e * K * N;
        BL += (size_t)e * K * N;
        if (BIAS) bias += (size_t)e * N;
    }
    const int tid = threadIdx.x;
    const int rowBase = blockIdx.y * 128;
    const int colBase = blockIdx.x * 128;

    const int rA = tid >> 2;
    const int ch = (tid & 3) * 8;
    const int r0i = rowBase + rA, r1i = rowBase + rA + 64;
    bool av0 = true, av1 = true;
    size_t aOff0, aOff1;
    if (MODE == 1) {
        av0 = r0i < cnt; av1 = r1i < cnt;
        aOff0 = (size_t)(av0 ? g_tok[base + r0i] : 0) * K;
        aOff1 = (size_t)(av1 ? g_tok[base + r1i] : 0) * K;
    } else if (MODE == 2) {
        av0 = r0i < cnt; av1 = r1i < cnt;
        aOff0 = (size_t)(base + (av0 ? r0i : 0)) * K;
        aOff1 = (size_t)(base + (av1 ? r1i : 0)) * K;
    } else {
        aOff0 = (size_t)r0i * K;
        aOff1 = (size_t)r1i * K;
    }
    const int kr = tid >> 4;
    const int bch = (tid & 15) * 8;

    const int lane = tid & 31, wid = tid >> 5;
    const int g  = lane >> 2;
    const int t4 = lane & 3;
    const int lane15 = lane & 15;
    const int warpM = (wid >> 2) * 64;
    const int warpN = (wid & 3) * 32;

    float c[4][4][4];
#pragma unroll
    for (int i = 0; i < 4; i++)
#pragma unroll
        for (int j = 0; j < 4; j++)
#pragma unroll
            for (int q = 0; q < 4; q++) c[i][j][q] = 0.f;

    auto load_stage = [&](int k0, __half* st) {
        __half* AsH = st;
        __half* AsL = st + A_HALFS;
        __half* BsH = st + 2 * A_HALFS;
        __half* BsL = BsH + B_HALFS;
        cp16h(&AsH[rA * LDAH + ch],        AH + aOff0 + k0 + ch, av0);
        cp16h(&AsH[(rA + 64) * LDAH + ch], AH + aOff1 + k0 + ch, av1);
        cp16h(&AsL[rA * LDAH + ch],        AL + aOff0 + k0 + ch, av0);
        cp16h(&AsL[(rA + 64) * LDAH + ch], AL + aOff1 + k0 + ch, av1);
        cp16h(&BsH[kr * LDBH + bch],        BH + (size_t)(k0 + kr) * N + colBase + bch, true);
        cp16h(&BsH[(kr + 16) * LDBH + bch], BH + (size_t)(k0 + kr + 16) * N + colBase + bch, true);
        cp16h(&BsL[kr * LDBH + bch],        BL + (size_t)(k0 + kr) * N + colBase + bch, true);
        cp16h(&BsL[(kr + 16) * LDBH + bch], BL + (size_t)(k0 + kr + 16) * N + colBase + bch, true);
    };

    const uint32_t smemAddr = (uint32_t)__cvta_generic_to_shared(smem);
    const int nIters = K / 32;
    load_stage(0, smem);
    cp_commit();

    for (int it = 0; it < nIters; it++) {
        const uint32_t st = smemAddr + (uint32_t)((it & 1) * STAGE_H * 2);
        if (it + 1 < nIters) {
            load_stage((it + 1) * 32, smem + (size_t)((it + 1) & 1) * STAGE_H);
            cp_commit();
            cp_wait<1>();
        } else {
            cp_wait<0>();
        }
        __syncthreads();

        const uint32_t aH = st + (uint32_t)(((warpM + lane15) * LDAH + (lane >> 4) * 8) * 2);
        const uint32_t aL = aH + A_HALFS * 2;
        const uint32_t bH = st + (uint32_t)(2 * A_HALFS * 2) +
                            (uint32_t)((lane15 * LDBH + warpN) * 2);
        const uint32_t bL = bH + B_HALFS * 2;

#pragma unroll
        for (int ks = 0; ks < 2; ks++) {
            const uint32_t aks = ks * 32;
            const uint32_t bks = ks * 16 * LDBH * 2;
            uint32_t bh[4][2], bl[4][2];
#pragma unroll
            for (int nt = 0; nt < 4; nt++) {
                ldx2t(bh[nt], bH + bks + nt * 16);
                ldx2t(bl[nt], bL + bks + nt * 16);
            }
#pragma unroll
            for (int mt = 0; mt < 4; mt++) {
                uint32_t ah[4], al[4];
                ldx4(ah, aH + aks + mt * 16 * LDAH * 2);
                ldx4(al, aL + aks + mt * 16 * LDAH * 2);
#pragma unroll
                for (int nt = 0; nt < 4; nt++) {
                    mma_f16(c[mt][nt], ah, bl[nt]);
                    mma_f16(c[mt][nt], al, bh[nt]);
                    mma_f16(c[mt][nt], ah, bh[nt]);
                }
            }
        }
        __syncthreads();
    }

    // epilogue
#pragma unroll
    for (int mt = 0; mt < 4; mt++) {
        const int r0 = rowBase + warpM + mt * 16 + g;
#pragma unroll
        for (int hh = 0; hh < 2; hh++) {
            const int r = r0 + hh * 8;
            if (MODE && r >= cnt) continue;
            const size_t orow = MODE ? (size_t)(base + r) : (size_t)r;
            const float* rp = RESID ? resid + (size_t)r * N : nullptr;
#pragma unroll
            for (int nt = 0; nt < 4; nt++) {
                const int col = colBase + warpN + nt * 8 + 2 * t4;
                float v0 = c[mt][nt][hh * 2 + 0];
                float v1 = c[mt][nt][hh * 2 + 1];
                if (BIAS) { v0 += bias[col]; v1 += bias[col + 1]; }
                if (RESID) { v0 += rp[col]; v1 += rp[col + 1]; }
                if (RELU) { v0 = fmaxf(v0, 0.f); v1 = fmaxf(v1, 0.f); }
                if (OUTH) {
                    __half h0 = __float2half_rn(v0), h1 = __float2half_rn(v1);
                    *(__half2*)(CoH + orow * N + col) = __halves2half2(h0, h1);
                    *(__half2*)(CoL + orow * N + col) = __halves2half2(
                        __float2half_rn(v0 - __half2float(h0)),
                        __float2half_rn(v1 - __half2float(h1)));
                } else {
                    float2 vv; vv.x = v0; vv.y = v1;
                    *(float2*)(Cf + orow * N + col) = vv;
                }
            }
        }
    }
}

// ---------------- 3xFP16 flash attention (pre-split qkv, cp.async producer) --------
#define ASTR 72
#define ATTN_KH 0
#define ATTN_KL (64 * ASTR)
#define ATTN_VH (2 * 64 * ASTR)
#define ATTN_VL (3 * 64 * ASTR)
#define ATTN_SMEM2 (4 * 64 * ASTR * 2)   // 36864 B (Q phase uses 2*128*ASTR = same)

__global__ __launch_bounds__(256, 2) void attn_mma(
    const __half* __restrict__ qkvH, const __half* __restrict__ qkvL)
{
    extern __shared__ __half sm[];
    const int qt = blockIdx.x;
    const int hd = blockIdx.y;
    const int b  = blockIdx.z;
    const int tid  = threadIdx.x;
    const int lane = tid & 31;
    const int w    = tid >> 5;
    const int g    = lane >> 2;
    const int t4   = lane & 3;
    const int lane15 = lane & 15;
    const int qRow0 = qt * 128;
    const __half* qbH = qkvH + (size_t)b * TSEQ * C3 + hd * HD;
    const __half* qbL = qkvL + (size_t)b * TSEQ * C3 + hd * HD;
    const uint32_t smb = (uint32_t)__cvta_generic_to_shared(sm);

    // ---- phase 1: Q tile 128x64 hi/lo via cp.async
    #pragma unroll
    for (int u = 0; u < 4; u++) {
        int lin = tid + u * 256;            // 1024 chunks per matrix
        int r = lin >> 3, c8 = (lin & 7) * 8;
        cp16h(&sm[r * ASTR + c8],              qbH + (size_t)(qRow0 + r) * C3 + c8, true);
        cp16h(&sm[128 * ASTR + r * ASTR + c8], qbL + (size_t)(qRow0 + r) * C3 + c8, true);
    }
    cp_commit();
    cp_wait<0>();
    __syncthreads();

    uint32_t qh[4][4], ql[4][4];
    {
        int row = (lane15 < 8) ? (8 * w + lane15) : (64 + 8 * w + lane15 - 8);
        uint32_t base = smb + (uint32_t)((row * ASTR + (lane >> 4) * 8) * 2);
        #pragma unroll
        for (int ks = 0; ks < 4; ks++) {
            ldx4(qh[ks], base + ks * 32);
            ldx4(ql[ks], base + ks * 32 + 128 * ASTR * 2);
        }
    }
    __syncthreads();

    float o[8][4];
    #pragma unroll
    for (int i = 0; i < 8; i++)
        #pragma unroll
        for (int j = 0; j < 4; j++) o[i][j] = 0.f;
    float m0 = -1e30f, m1 = -1e30f, l0 = 0.f, l1 = 0.f;
    const int row0 = qRow0 + 8 * w + g;
    const int row1 = row0 + 64;
    const int row1max = qRow0 + 64 + 8 * w + 7;
    const float scale = 0.125f;
    const int nTiles = qt * 2 + 2;

    for (int t = 0; t < nTiles; t++) {
        const int j0 = t * 64;
        // ---- K/V tile hi/lo via cp.async (512 chunks per matrix, 4 matrices)
        #pragma unroll
        for (int u = 0; u < 2; u++) {
            int lin = tid + u * 256;
            int r = lin >> 3, c8 = (lin & 7) * 8;
            size_t krow = (size_t)(j0 + r) * C3;
            cp16h(&sm[ATTN_KH + r * ASTR + c8], qbH + CDIM + krow + c8, true);
            cp16h(&sm[ATTN_KL + r * ASTR + c8], qbL + CDIM + krow + c8, true);
            cp16h(&sm[ATTN_VH + r * ASTR + c8], qbH + 2 * CDIM + krow + c8, true);
            cp16h(&sm[ATTN_VL + r * ASTR + c8], qbL + 2 * CDIM + krow + c8, true);
        }
        cp_commit();
        cp_wait<0>();
        __syncthreads();

        if (j0 <= row1max) {
            float s[8][4];
            #pragma unroll
            for (int i = 0; i < 8; i++)
                #pragma unroll
                for (int j = 0; j < 4; j++) s[i][j] = 0.f;
            {
                const uint32_t kb = smb + (uint32_t)((((lane15 & 7) * ASTR) + (lane15 >> 3) * 8) * 2);
                #pragma unroll
                for (int nt = 0; nt < 8; nt++) {
                    const uint32_t knt = kb + (uint32_t)(nt * 8 * ASTR * 2);
                    #pragma unroll
                    for (int ks = 0; ks < 4; ks++) {
                        uint32_t kh2[2], kl2[2];
                        ldx2(kh2, knt + ks * 32 + ATTN_KH * 2);
                        ldx2(kl2, knt + ks * 32 + ATTN_KL * 2);
                        mma_f16(s[nt], qh[ks], kl2);
                        mma_f16(s[nt], ql[ks], kh2);
                        mma_f16(s[nt], qh[ks], kh2);
                    }
                }
            }
            float mloc0 = -1e30f, mloc1 = -1e30f;
            #pragma unroll
            for (int nt = 0; nt < 8; nt++) {
                int kg = j0 + nt * 8 + 2 * t4;
                s[nt][0] = (kg     <= row0) ? s[nt][0] * scale : -1e30f;
                s[nt][1] = (kg + 1 <= row0) ? s[nt][1] * scale : -1e30f;
                s[nt][2] = (kg     <= row1) ? s[nt][2] * scale : -1e30f;
                s[nt][3] = (kg + 1 <= row1) ? s[nt][3] * scale : -1e30f;
                mloc0 = fmaxf(mloc0, fmaxf(s[nt][0], s[nt][1]));
                mloc1 = fmaxf(mloc1, fmaxf(s[nt][2], s[nt][3]));
            }
            mloc0 = fmaxf(mloc0, __shfl_xor_sync(0xffffffffu, mloc0, 1));
            mloc0 = fmaxf(mloc0, __shfl_xor_sync(0xffffffffu, mloc0, 2));
            mloc1 = fmaxf(mloc1, __shfl_xor_sync(0xffffffffu, mloc1, 1));
            mloc1 = fmaxf(mloc1, __shfl_xor_sync(0xffffffffu, mloc1, 2));
            float mn0 = fmaxf(m0, mloc0), mn1 = fmaxf(m1, mloc1);
            float a0 = __expf(m0 - mn0), a1 = __expf(m1 - mn1);
            float ls0 = 0.f, ls1 = 0.f;
            #pragma unroll
            for (int nt = 0; nt < 8; nt++) {
                s[nt][0] = __expf(s[nt][0] - mn0);
                s[nt][1] = __expf(s[nt][1] - mn0);
                s[nt][2] = __expf(s[nt][2] - mn1);
                s[nt][3] = __expf(s[nt][3] - mn1);
                ls0 += s[nt][0] + s[nt][1];
                ls1 += s[nt][2] + s[nt][3];
            }
            ls0 += __shfl_xor_sync(0xffffffffu, ls0, 1);
            ls0 += __shfl_xor_sync(0xffffffffu, ls0, 2);
            ls1 += __shfl_xor_sync(0xffffffffu, ls1, 1);
            ls1 += __shfl_xor_sync(0xffffffffu, ls1, 2);
            l0 = l0 * a0 + ls0;  l1 = l1 * a1 + ls1;
            m0 = mn0;  m1 = mn1;
            #pragma unroll
            for (int dt = 0; dt < 8; dt++) {
                o[dt][0] *= a0; o[dt][1] *= a0;
                o[dt][2] *= a1; o[dt][3] *= a1;
            }
            const uint32_t vb = smb + (uint32_t)((lane15 * ASTR) * 2);
            #pragma unroll
            for (int ks = 0; ks < 4; ks++) {
                uint32_t ph[4], pl[4];
                #pragma unroll
                for (int half16 = 0; half16 < 2; half16++) {
                    int nt = ks * 2 + half16;
                    __half h0 = __float2half_rn(s[nt][0]);
                    __half h1 = __float2half_rn(s[nt][1]);
                    __half h2 = __float2half_rn(s[nt][2]);
                    __half h3 = __float2half_rn(s[nt][3]);
                    ph[half16 * 2 + 0] = packh(h0, h1);
                    ph[half16 * 2 + 1] = packh(h2, h3);
                    pl[half16 * 2 + 0] = packh(
                        __float2half_rn(s[nt][0] - __half2float(h0)),
                        __float2half_rn(s[nt][1] - __half2float(h1)));
                    pl[half16 * 2 + 1] = packh(
                        __float2half_rn(s[nt][2] - __half2float(h2)),
                        __float2half_rn(s[nt][3] - __half2float(h3)));
                }
                uint32_t pha[4] = { ph[0], ph[1], ph[2], ph[3] };
                uint32_t pla[4] = { pl[0], pl[1], pl[2], pl[3] };
                const uint32_t vks = vb + (uint32_t)(ks * 16 * ASTR * 2);
                #pragma unroll
                for (int dt = 0; dt < 8; dt++) {
                    uint32_t vh2[2], vl2[2];
                    ldx2t(vh2, vks + dt * 16 + ATTN_VH * 2);
                    ldx2t(vl2, vks + dt * 16 + ATTN_VL * 2);
                    mma_f16(o[dt], pha, vl2);
                    mma_f16(o[dt], pla, vh2);
                    mma_f16(o[dt], pha, vh2);
                }
            }
        }
        __syncthreads();
    }

    // epilogue: write y as hi/lo halves for the proj GEMM
    const float inv0 = 1.f / l0, inv1 = 1.f / l1;
    const size_t y0off = (size_t)(b * TSEQ + row0) * CDIM + hd * HD;
    const size_t y1off = (size_t)(b * TSEQ + row1) * CDIM + hd * HD;
    #pragma unroll
    for (int dt = 0; dt < 8; dt++) {
        int col = dt * 8 + 2 * t4;
        float v00 = o[dt][0] * inv0, v01 = o[dt][1] * inv0;
        float v10 = o[dt][2] * inv1, v11 = o[dt][3] * inv1;
        __half h00 = __float2half_rn(v00), h01 = __float2half_rn(v01);
        __half h10 = __float2half_rn(v10), h11 = __float2half_rn(v11);
        *(__half2*)(g_yH + y0off + col) = __halves2half2(h00, h01);
        *(__half2*)(g_yL + y0off + col) = __halves2half2(
            __float2half_rn(v00 - __half2float(h00)),
            __float2half_rn(v01 - __half2float(h01)));
        *(__half2*)(g_yH + y1off + col) = __halves2half2(h10, h11);
        *(__half2*)(g_yL + y1off + col) = __halves2half2(
            __float2half_rn(v10 - __half2float(h10)),
            __float2half_rn(v11 - __half2float(h11)));
    }
}

// ---------------- router (reads hi+lo z) -------------------------------------------
__global__ __launch_bounds__(256) void router_kernel(
    const float* __restrict__ Wr, const float* __restrict__ br)
{
    const int warp = (blockIdx.x * blockDim.x + threadIdx.x) >> 5;
    const int lane = threadIdx.x & 31;
    if (warp >= NTOK) return;
    float p[NEXP];
#pragma unroll
    for (int e = 0; e < NEXP; e++) p[e] = 0.f;
    for (int c = lane; c < CDIM; c += 32) {
        float zv = __half2float(g_zH[(size_t)warp * CDIM + c]) +
                   __half2float(g_zL[(size_t)warp * CDIM + c]);
        const float* wrow = Wr + c * NEXP;
#pragma unroll
        for (int e = 0; e < NEXP; e++) p[e] += zv * wrow[e];
    }
#pragma unroll
    for (int off = 16; off; off >>= 1)
#pragma unroll
        for (int e = 0; e < NEXP; e++) p[e] += __shfl_xor_sync(0xffffffffu, p[e], off);
    if (lane == 0) {
        float lg[NEXP];
#pragma unroll
        for (int e = 0; e < NEXP; e++) lg[e] = p[e] + br[e];
        int e0 = 0;
#pragma unroll
        for (int e = 1; e < NEXP; e++) if (lg[e] > lg[e0]) e0 = e;
        int e1 = (e0 == 0) ? 1 : 0;
#pragma unroll
        for (int e = 0; e < NEXP; e++) if (e != e0 && lg[e] > lg[e1]) e1 = e;
        float w0 = 1.f / (1.f + __expf(lg[e1] - lg[e0]));
        g_wgt[warp * 2] = w0;
        g_wgt[warp * 2 + 1] = 1.f - w0;
        g_eidx[warp * 2] = e0;
        g_eidx[warp * 2 + 1] = e1;
        atomicAdd(&g_cnt[e0], 1);
        atomicAdd(&g_cnt[e1], 1);
    }
}

__global__ void zero_kernel() {
    int t = threadIdx.x;
    if (t < NEXP) { g_cnt[t] = 0; g_cur[t] = 0; }
}

__global__ void prefix_kernel() {
    int s = 0;
    for (int e = 0; e < NEXP; e++) { g_off[e] = s; s += g_cnt[e]; }
}

__global__ __launch_bounds__(256) void assign_kernel() {
    int n = blockIdx.x * blockDim.x + threadIdx.x;
    if (n >= NTOK) return;
#pragma unroll
    for (int k = 0; k < 2; k++) {
        int e = g_eidx[n * 2 + k];
        int pos = atomicAdd(&g_cur[e], 1);
        int slot = g_off[e] + pos;
        g_slot[n * 2 + k] = slot;
        g_tok[slot] = n;
    }
}

// ---------------- final: out = x1 + sum_k w_k * (ye_k + b2[e_k]) -------------------
__global__ __launch_bounds__(256) void final_kernel(
    const float* __restrict__ b2, float* __restrict__ out)
{
    int i = blockIdx.x * blockDim.x + threadIdx.x;
    const int total = NTOK * CDIM / 4;
    if (i >= total) return;
    int n = i / (CDIM / 4);
    int c = (i % (CDIM / 4)) * 4;
    float w0 = g_wgt[n * 2], w1 = g_wgt[n * 2 + 1];
    int e0 = g_eidx[n * 2], e1 = g_eidx[n * 2 + 1];
    int s0 = g_slot[n * 2], s1 = g_slot[n * 2 + 1];
    float4 xv  = *(const float4*)&g_x1[(size_t)n * CDIM + c];
    float4 y0  = *(const float4*)&g_ye[(size_t)s0 * CDIM + c];
    float4 y1  = *(const float4*)&g_ye[(size_t)s1 * CDIM + c];
    float4 b0  = *(const float4*)&b2[(size_t)e0 * CDIM + c];
    float4 b1v = *(const float4*)&b2[(size_t)e1 * CDIM + c];
    float4 r;
    r.x = xv.x + w0 * (y0.x + b0.x) + w1 * (y1.x + b1v.x);
    r.y = xv.y + w0 * (y0.y + b0.y) + w1 * (y1.y + b1v.y);
    r.z = xv.z + w0 * (y0.z + b0.z) + w1 * (y1.z + b1v.z);
    r.w = xv.w + w0 * (y0.w + b0.w) + w1 * (y1.w + b1v.w);
    *(float4*)&out[(size_t)n * CDIM + c] = r;
}

// ---------------- launch -----------------------------------------------------------
extern "C" void kernel_launch(void* const* d_in, const int* in_sizes, int n_in,
                              void* d_out, int out_size)
{
    const float* x      = (const float*)d_in[0];
    const float* ln1_g  = (const float*)d_in[1];
    const float* ln1_b  = (const float*)d_in[2];
    const float* Wqkv   = (const float*)d_in[3];
    const float* bqkv   = (const float*)d_in[4];
    const float* Wproj  = (const float*)d_in[5];
    const float* bproj  = (const float*)d_in[6];
    const float* ln2_g  = (const float*)d_in[7];
    const float* ln2_b  = (const float*)d_in[8];
    const float* Wr     = (const float*)d_in[9];
    const float* br     = (const float*)d_in[10];
    const float* W1     = (const float*)d_in[11];
    const float* b1     = (const float*)d_in[12];
    const float* W2     = (const float*)d_in[13];
    const float* b2     = (const float*)d_in[14];
    float* out = (float*)d_out;

    static bool inited = false;
    static float *p_x1, *p_ye;
    static __half *p_qkvH, *p_qkvL;
    static __half *p_hH, *p_hL, *p_yH, *p_yL, *p_zH, *p_zL, *p_hidH, *p_hidL;
    static __half *p_WqkvH, *p_WqkvL, *p_WprojH, *p_WprojL;
    static __half *p_W1H, *p_W1L, *p_W2H, *p_W2L;
    if (!inited) {
        cudaGetSymbolAddress((void**)&p_x1,  g_x1);
        cudaGetSymbolAddress((void**)&p_ye,  g_ye);
        cudaGetSymbolAddress((void**)&p_qkvH, g_qkvH);
        cudaGetSymbolAddress((void**)&p_qkvL, g_qkvL);
        cudaGetSymbolAddress((void**)&p_hH,  g_hH);
        cudaGetSymbolAddress((void**)&p_hL,  g_hL);
        cudaGetSymbolAddress((void**)&p_yH,  g_yH);
        cudaGetSymbolAddress((void**)&p_yL,  g_yL);
        cudaGetSymbolAddress((void**)&p_zH,  g_zH);
        cudaGetSymbolAddress((void**)&p_zL,  g_zL);
        cudaGetSymbolAddress((void**)&p_hidH, g_hidH);
        cudaGetSymbolAddress((void**)&p_hidL, g_hidL);
        cudaGetSymbolAddress((void**)&p_WqkvH, g_WqkvH);
        cudaGetSymbolAddress((void**)&p_WqkvL, g_WqkvL);
        cudaGetSymbolAddress((void**)&p_WprojH, g_WprojH);
        cudaGetSymbolAddress((void**)&p_WprojL, g_WprojL);
        cudaGetSymbolAddress((void**)&p_W1H, g_W1H);
        cudaGetSymbolAddress((void**)&p_W1L, g_W1L);
        cudaGetSymbolAddress((void**)&p_W2H, g_W2H);
        cudaGetSymbolAddress((void**)&p_W2L, g_W2L);
        cudaFuncSetAttribute(attn_mma,
                             cudaFuncAttributeMaxDynamicSharedMemorySize, ATTN_SMEM2);
        cudaFuncSetAttribute(gemm_f16pre<true, false, false, 0, true>,
                             cudaFuncAttributeMaxDynamicSharedMemorySize, GEMM_SMEM);
        cudaFuncSetAttribute(gemm_f16pre<true, false, true, 0, false>,
                             cudaFuncAttributeMaxDynamicSharedMemorySize, GEMM_SMEM);
        cudaFuncSetAttribute(gemm_f16pre<true, true, false, 1, true>,
                             cudaFuncAttributeMaxDynamicSharedMemorySize, GEMM_SMEM);
        cudaFuncSetAttribute(gemm_f16pre<false, false, false, 2, false>,
                             cudaFuncAttributeMaxDynamicSharedMemorySize, GEMM_SMEM);
        inited = true;
    }

    // 0. pre-split weights into hi/lo halves
    splitw_kernel<<<(CDIM * C3 / 4 + 255) / 256, 256>>>(Wqkv, p_WqkvH, p_WqkvL, CDIM * C3 / 4);
    splitw_kernel<<<(CDIM * CDIM / 4 + 255) / 256, 256>>>(Wproj, p_WprojH, p_WprojL, CDIM * CDIM / 4);
    splitw_kernel<<<(NEXP * CDIM * DFF / 4 + 255) / 256, 256>>>(W1, p_W1H, p_W1L, NEXP * CDIM * DFF / 4);
    splitw_kernel<<<(NEXP * DFF * CDIM / 4 + 255) / 256, 256>>>(W2, p_W2H, p_W2L, NEXP * DFF * CDIM / 4);

    // 1. LN1 -> hi/lo halves
    ln_half<<<NTOK, 256>>>(x, ln1_g, ln1_b, p_hH, p_hL);
    // 2. QKV GEMM -> hi/lo halves
    gemm_f16pre<true, false, false, 0, true><<<dim3(C3 / 128, NTOK / 128), 256, GEMM_SMEM>>>(
        p_hH, p_hL, p_WqkvH, p_WqkvL, bqkv, nullptr, nullptr, p_qkvH, p_qkvL, C3, CDIM);
    // 3. flash attention (reads pre-split qkv, writes yH/yL)
    attn_mma<<<dim3(TSEQ / 128, NH, 4), 256, ATTN_SMEM2>>>(p_qkvH, p_qkvL);
    // 4. proj + residual
    gemm_f16pre<true, false, true, 0, false><<<dim3(CDIM / 128, NTOK / 128), 256, GEMM_SMEM>>>(
        p_yH, p_yL, p_WprojH, p_WprojL, bproj, x, p_x1, nullptr, nullptr, CDIM, CDIM);
    // 5. LN2 -> hi/lo halves
    ln_half<<<NTOK, 256>>>(p_x1, ln2_g, ln2_b, p_zH, p_zL);
    // 6. routing
    zero_kernel<<<1, 32>>>();
    router_kernel<<<NTOK / 8, 256>>>(Wr, br);
    prefix_kernel<<<1, 1>>>();
    assign_kernel<<<NTOK / 256, 256>>>();
    // 7. MoE grouped GEMMs
    gemm_f16pre<true, true, false, 1, true><<<dim3(DFF / 128, NTOK / 128, NEXP), 256, GEMM_SMEM>>>(
        p_zH, p_zL, p_W1H, p_W1L, b1, nullptr, nullptr, p_hidH, p_hidL, DFF, CDIM);
    gemm_f16pre<false, false, false, 2, false><<<dim3(CDIM / 128, NTOK / 128, NEXP), 256, GEMM_SMEM>>>(
        p_hidH, p_hidL, p_W2H, p_W2L, nullptr, nullptr, p_ye, nullptr, nullptr, CDIM, DFF);
    // 8. weighted gather + residual
    final_kernel<<<(NTOK * CDIM / 4 + 255) / 256, 256>>>(b2, out);
}